// round 5
// baseline (speedup 1.0000x reference)
#include <cuda_runtime.h>
#include <cstdint>
#include <cstddef>

// Problem constants
#define H_DIM   2048
#define S_LEN   2048
#define B_SZ    2
#define NHEADS  16
#define NKVH    8
#define HD      128
#define FF_DIM  5632
#define MROWS   (B_SZ * S_LEN)          // 4096
#define QKV_LD  4096                    // q(2048) | k(1024) | v(1024)
#define ATT_SCALE 0.08838834764831845f  // 1/sqrt(128)

// ---------------------------------------------------------------------------
// Scratch (allocation is forbidden; __device__ globals are the sanctioned path)
// ---------------------------------------------------------------------------
__device__ float g_xn  [(size_t)MROWS * H_DIM];   // rmsnorm output (reused twice)
__device__ float g_qkv [(size_t)MROWS * QKV_LD];
__device__ float g_attn[(size_t)MROWS * H_DIM];
__device__ float g_h   [(size_t)MROWS * H_DIM];   // residual-1 output
__device__ float g_gate[(size_t)MROWS * FF_DIM];
__device__ float g_up  [(size_t)MROWS * FF_DIM];
__device__ float g_ff  [(size_t)MROWS * FF_DIM];

// ---------------------------------------------------------------------------
// RMSNorm: one block per row (H=2048), 256 threads, float4
// ---------------------------------------------------------------------------
__global__ __launch_bounds__(256) void rmsnorm_k(
    const float* __restrict__ x, const float* __restrict__ w, float* __restrict__ y)
{
    const int row = blockIdx.x;
    const float4* xr = (const float4*)(x + (size_t)row * H_DIM);
    float4*       yr = (float4*)(y + (size_t)row * H_DIM);
    const float4* w4 = (const float4*)w;
    const int tid = threadIdx.x;

    float4 v0 = xr[tid];
    float4 v1 = xr[tid + 256];
    float s = v0.x*v0.x + v0.y*v0.y + v0.z*v0.z + v0.w*v0.w
            + v1.x*v1.x + v1.y*v1.y + v1.z*v1.z + v1.w*v1.w;

    #pragma unroll
    for (int off = 16; off; off >>= 1) s += __shfl_xor_sync(0xffffffffu, s, off);

    __shared__ float red[8];
    if ((tid & 31) == 0) red[tid >> 5] = s;
    __syncthreads();
    float tot = red[0] + red[1] + red[2] + red[3] + red[4] + red[5] + red[6] + red[7];
    const float inv = rsqrtf(tot * (1.0f / H_DIM) + 1e-6f);

    float4 w0 = w4[tid], w1 = w4[tid + 256];
    float4 o0, o1;
    o0.x = v0.x * inv * w0.x; o0.y = v0.y * inv * w0.y;
    o0.z = v0.z * inv * w0.z; o0.w = v0.w * inv * w0.w;
    o1.x = v1.x * inv * w1.x; o1.y = v1.y * inv * w1.y;
    o1.z = v1.z * inv * w1.z; o1.w = v1.w * inv * w1.w;
    yr[tid] = o0;
    yr[tid + 256] = o1;
}

// ---------------------------------------------------------------------------
// NT GEMM: C[m,n] = sum_k A[m,k] * B[n,k]  (+ optional residual, res ld == ldc)
// BM=BN=128, BK=16, 256 threads, 8x8 per thread.
// Grid: (N/128, M/128). All shapes here are multiples of 128 / K mult of 16.
// ---------------------------------------------------------------------------
__global__ __launch_bounds__(256) void gemm_nt(
    const float* __restrict__ A, int lda,
    const float* __restrict__ B, int ldb,
    const float* __restrict__ Res,
    float* __restrict__ C, int ldc, int K)
{
    __shared__ __align__(16) float As[16][132];
    __shared__ __align__(16) float Bs[16][132];

    const int tid = threadIdx.x;
    const int tx = tid & 15, ty = tid >> 4;
    const int m0 = blockIdx.y * 128;
    const int n0 = blockIdx.x * 128;

    const float* Ag = A + (size_t)m0 * lda;
    const float* Bg = B + (size_t)n0 * ldb;

    float acc[8][8];
    #pragma unroll
    for (int i = 0; i < 8; i++)
        #pragma unroll
        for (int j = 0; j < 8; j++) acc[i][j] = 0.0f;

    const int r0 = tid >> 2;         // 0..63
    const int c4 = (tid & 3) << 2;   // 0,4,8,12

    for (int k0 = 0; k0 < K; k0 += 16) {
        float4 a0 = *(const float4*)(Ag + (size_t)r0        * lda + k0 + c4);
        float4 a1 = *(const float4*)(Ag + (size_t)(r0 + 64) * lda + k0 + c4);
        float4 b0 = *(const float4*)(Bg + (size_t)r0        * ldb + k0 + c4);
        float4 b1 = *(const float4*)(Bg + (size_t)(r0 + 64) * ldb + k0 + c4);

        As[c4+0][r0] = a0.x; As[c4+1][r0] = a0.y; As[c4+2][r0] = a0.z; As[c4+3][r0] = a0.w;
        As[c4+0][r0+64] = a1.x; As[c4+1][r0+64] = a1.y; As[c4+2][r0+64] = a1.z; As[c4+3][r0+64] = a1.w;
        Bs[c4+0][r0] = b0.x; Bs[c4+1][r0] = b0.y; Bs[c4+2][r0] = b0.z; Bs[c4+3][r0] = b0.w;
        Bs[c4+0][r0+64] = b1.x; Bs[c4+1][r0+64] = b1.y; Bs[c4+2][r0+64] = b1.z; Bs[c4+3][r0+64] = b1.w;
        __syncthreads();

        #pragma unroll
        for (int kk = 0; kk < 16; kk++) {
            float a[8], b[8];
            *(float4*)(a)     = *(const float4*)&As[kk][ty * 8];
            *(float4*)(a + 4) = *(const float4*)&As[kk][ty * 8 + 4];
            *(float4*)(b)     = *(const float4*)&Bs[kk][tx * 8];
            *(float4*)(b + 4) = *(const float4*)&Bs[kk][tx * 8 + 4];
            #pragma unroll
            for (int i = 0; i < 8; i++)
                #pragma unroll
                for (int j = 0; j < 8; j++)
                    acc[i][j] += a[i] * b[j];
        }
        __syncthreads();
    }

    #pragma unroll
    for (int i = 0; i < 8; i++) {
        const size_t m = (size_t)(m0 + ty * 8 + i);
        float* cp = C + m * ldc + n0 + tx * 8;
        float4 v0 = make_float4(acc[i][0], acc[i][1], acc[i][2], acc[i][3]);
        float4 v1 = make_float4(acc[i][4], acc[i][5], acc[i][6], acc[i][7]);
        if (Res) {
            const float* rp = Res + m * ldc + n0 + tx * 8;
            float4 e0 = *(const float4*)rp;
            float4 e1 = *(const float4*)(rp + 4);
            v0.x += e0.x; v0.y += e0.y; v0.z += e0.z; v0.w += e0.w;
            v1.x += e1.x; v1.y += e1.y; v1.z += e1.z; v1.w += e1.w;
        }
        *(float4*)cp = v0;
        *(float4*)(cp + 4) = v1;
    }
}

// ---------------------------------------------------------------------------
// Causal flash attention, fp32, GQA (kv head = h >> 1).
// Grid (32, 16, 2): q-tile 64, k-tile 64. Block 256 (16x16 logical).
// Each thread: 4 q-rows (ty*4+i) x [4 score cols (tx*4+j) | 8 out cols (tx*8+j)].
// Smem: Qs[64][128] + Ks[64][132] + Vs[64][128] + Ps[64][64] = 113 KB dynamic.
// ---------------------------------------------------------------------------
#define FLASH_SMEM ((64*128 + 64*132 + 64*128 + 64*64) * 4)

__global__ __launch_bounds__(256) void flash_k(
    const float* __restrict__ qkv, float* __restrict__ out)
{
    extern __shared__ float sm[];
    float* Qs = sm;                 // [64][128]
    float* Ks = Qs + 64 * 128;      // [64][132] (padded vs bank conflicts)
    float* Vs = Ks + 64 * 132;      // [64][128]
    float* Ps = Vs + 64 * 128;      // [64][64]

    const int qt = gridDim.x - 1 - blockIdx.x;   // high q-tiles first (causal balance)
    const int h  = blockIdx.y;
    const int b  = blockIdx.z;
    const int kvh = h >> 1;                      // GROUPS = 2
    const int q0 = qt * 64;
    const int tid = threadIdx.x;
    const int tx = tid & 15, ty = tid >> 4;

    const float* qbase = qkv + ((size_t)(b * S_LEN + q0)) * QKV_LD + h * HD;
    const float* kbase = qkv + ((size_t)(b * S_LEN)) * QKV_LD + 2048 + kvh * HD;
    const float* vbase = kbase + 1024;

    // Load Q tile (pre-scaled by 1/sqrt(HD))
    #pragma unroll
    for (int t = 0; t < 8; t++) {
        int idx = tid + t * 256;
        int r = idx >> 5;
        int d4 = (idx & 31) << 2;
        float4 v = *(const float4*)(qbase + (size_t)r * QKV_LD + d4);
        v.x *= ATT_SCALE; v.y *= ATT_SCALE; v.z *= ATT_SCALE; v.w *= ATT_SCALE;
        *(float4*)&Qs[r * 128 + d4] = v;
    }

    float m[4], l[4], o[4][8];
    #pragma unroll
    for (int i = 0; i < 4; i++) {
        m[i] = -1e30f; l[i] = 0.0f;
        #pragma unroll
        for (int j = 0; j < 8; j++) o[i][j] = 0.0f;
    }

    for (int kt = 0; kt <= qt; kt++) {
        const int k0 = kt * 64;
        __syncthreads();  // protect Ks/Vs/Ps reuse
        #pragma unroll
        for (int t = 0; t < 8; t++) {
            int idx = tid + t * 256;
            int r = idx >> 5;
            int d4 = (idx & 31) << 2;
            *(float4*)&Ks[r * 132 + d4] = *(const float4*)(kbase + (size_t)(k0 + r) * QKV_LD + d4);
            *(float4*)&Vs[r * 128 + d4] = *(const float4*)(vbase + (size_t)(k0 + r) * QKV_LD + d4);
        }
        __syncthreads();

        // --- scores: s[i][j] = q_row(ty*4+i) . k_row(tx*4+j) ---
        float s4[4][4];
        #pragma unroll
        for (int i = 0; i < 4; i++)
            #pragma unroll
            for (int j = 0; j < 4; j++) s4[i][j] = 0.0f;

        const float* qp = &Qs[(ty * 4) * 128];
        const float* kp = &Ks[(tx * 4) * 132];
        #pragma unroll 8
        for (int d = 0; d < 128; d += 4) {
            float4 qv[4], kv[4];
            #pragma unroll
            for (int i = 0; i < 4; i++) qv[i] = *(const float4*)(qp + i * 128 + d);
            #pragma unroll
            for (int j = 0; j < 4; j++) kv[j] = *(const float4*)(kp + j * 132 + d);
            #pragma unroll
            for (int i = 0; i < 4; i++)
                #pragma unroll
                for (int j = 0; j < 4; j++)
                    s4[i][j] += qv[i].x * kv[j].x + qv[i].y * kv[j].y
                              + qv[i].z * kv[j].z + qv[i].w * kv[j].w;
        }

        if (kt == qt) {  // diagonal tile: mask kpos > qpos
            #pragma unroll
            for (int i = 0; i < 4; i++)
                #pragma unroll
                for (int j = 0; j < 4; j++)
                    if (k0 + tx * 4 + j > q0 + ty * 4 + i) s4[i][j] = -1e30f;
        }

        // --- online softmax (rows owned by the 16 threads sharing ty) ---
        #pragma unroll
        for (int i = 0; i < 4; i++) {
            float tm = fmaxf(fmaxf(s4[i][0], s4[i][1]), fmaxf(s4[i][2], s4[i][3]));
            #pragma unroll
            for (int off = 8; off; off >>= 1)
                tm = fmaxf(tm, __shfl_xor_sync(0xffffffffu, tm, off));
            const float nm = fmaxf(m[i], tm);
            const float alpha = __expf(m[i] - nm);
            m[i] = nm;
            float p0 = __expf(s4[i][0] - nm);
            float p1 = __expf(s4[i][1] - nm);
            float p2 = __expf(s4[i][2] - nm);
            float p3 = __expf(s4[i][3] - nm);
            float rs = p0 + p1 + p2 + p3;
            #pragma unroll
            for (int off = 8; off; off >>= 1)
                rs += __shfl_xor_sync(0xffffffffu, rs, off);
            l[i] = l[i] * alpha + rs;
            #pragma unroll
            for (int j = 0; j < 8; j++) o[i][j] *= alpha;
            *(float4*)&Ps[(ty * 4 + i) * 64 + tx * 4] = make_float4(p0, p1, p2, p3);
        }
        __syncthreads();

        // --- O += P @ V : thread covers out cols tx*8..tx*8+7 ---
        const float* vp = &Vs[tx * 8];
        #pragma unroll 4
        for (int k4 = 0; k4 < 64; k4 += 4) {
            float4 pr[4];
            #pragma unroll
            for (int i = 0; i < 4; i++)
                pr[i] = *(const float4*)&Ps[(ty * 4 + i) * 64 + k4];
            #pragma unroll
            for (int kk = 0; kk < 4; kk++) {
                float4 v0 = *(const float4*)(vp + (size_t)(k4 + kk) * 128);
                float4 v1 = *(const float4*)(vp + (size_t)(k4 + kk) * 128 + 4);
                #pragma unroll
                for (int i = 0; i < 4; i++) {
                    float p = (kk == 0) ? pr[i].x : (kk == 1) ? pr[i].y
                            : (kk == 2) ? pr[i].z : pr[i].w;
                    o[i][0] += p * v0.x; o[i][1] += p * v0.y;
                    o[i][2] += p * v0.z; o[i][3] += p * v0.w;
                    o[i][4] += p * v1.x; o[i][5] += p * v1.y;
                    o[i][6] += p * v1.z; o[i][7] += p * v1.w;
                }
            }
        }
    }

    // write O / l  → attn buffer laid out [row][h*128+d]
    #pragma unroll
    for (int i = 0; i < 4; i++) {
        const float inv = 1.0f / l[i];
        float* op = out + ((size_t)(b * S_LEN + q0 + ty * 4 + i)) * H_DIM + h * HD + tx * 8;
        *(float4*)op       = make_float4(o[i][0]*inv, o[i][1]*inv, o[i][2]*inv, o[i][3]*inv);
        *(float4*)(op + 4) = make_float4(o[i][4]*inv, o[i][5]*inv, o[i][6]*inv, o[i][7]*inv);
    }
}

// ---------------------------------------------------------------------------
// SiLU(gate) * up, float4 elementwise
// ---------------------------------------------------------------------------
__global__ __launch_bounds__(256) void silu_mul_k(
    const float4* __restrict__ g, const float4* __restrict__ u,
    float4* __restrict__ y, int n4)
{
    int i = blockIdx.x * 256 + threadIdx.x;
    if (i >= n4) return;
    float4 a = g[i], b = u[i], r;
    r.x = a.x / (1.0f + __expf(-a.x)) * b.x;
    r.y = a.y / (1.0f + __expf(-a.y)) * b.y;
    r.z = a.z / (1.0f + __expf(-a.z)) * b.z;
    r.w = a.w / (1.0f + __expf(-a.w)) * b.w;
    y[i] = r;
}

// ---------------------------------------------------------------------------
// Launch
// ---------------------------------------------------------------------------
extern "C" void kernel_launch(void* const* d_in, const int* in_sizes, int n_in,
                              void* d_out, int out_size)
{
    const float* hidden = (const float*)d_in[0];
    // d_in[1] = attention_mask (pure causal — implemented directly)
    const float* q_w    = (const float*)d_in[2];
    const float* k_w    = (const float*)d_in[3];
    const float* v_w    = (const float*)d_in[4];
    const float* o_w    = (const float*)d_in[5];
    const float* gate_w = (const float*)d_in[6];
    const float* up_w   = (const float*)d_in[7];
    const float* down_w = (const float*)d_in[8];
    const float* ln1    = (const float*)d_in[9];
    const float* ln2    = (const float*)d_in[10];
    float* out = (float*)d_out;

    float *xn, *qkv, *attn, *hbuf, *gate, *up, *ff;
    cudaGetSymbolAddress((void**)&xn,   g_xn);
    cudaGetSymbolAddress((void**)&qkv,  g_qkv);
    cudaGetSymbolAddress((void**)&attn, g_attn);
    cudaGetSymbolAddress((void**)&hbuf, g_h);
    cudaGetSymbolAddress((void**)&gate, g_gate);
    cudaGetSymbolAddress((void**)&up,   g_up);
    cudaGetSymbolAddress((void**)&ff,   g_ff);

    cudaFuncSetAttribute(flash_k, cudaFuncAttributeMaxDynamicSharedMemorySize, FLASH_SMEM);

    // 1) rmsnorm(hidden) -> xn
    rmsnorm_k<<<MROWS, 256>>>(hidden, ln1, xn);

    // 2) QKV projections into fused buffer [row][4096]
    gemm_nt<<<dim3(16, 32), 256>>>(xn, H_DIM, q_w, H_DIM, nullptr, qkv,        QKV_LD, H_DIM);
    gemm_nt<<<dim3( 8, 32), 256>>>(xn, H_DIM, k_w, H_DIM, nullptr, qkv + 2048, QKV_LD, H_DIM);
    gemm_nt<<<dim3( 8, 32), 256>>>(xn, H_DIM, v_w, H_DIM, nullptr, qkv + 3072, QKV_LD, H_DIM);

    // 3) causal flash attention -> attn [row][nh*hd]
    flash_k<<<dim3(S_LEN / 64, NHEADS, B_SZ), 256, FLASH_SMEM>>>(qkv, attn);

    // 4) O projection + residual -> hbuf
    gemm_nt<<<dim3(16, 32), 256>>>(attn, H_DIM, o_w, H_DIM, hidden, hbuf, H_DIM, H_DIM);

    // 5) rmsnorm(hbuf) -> xn
    rmsnorm_k<<<MROWS, 256>>>(hbuf, ln2, xn);

    // 6) gate/up projections
    gemm_nt<<<dim3(44, 32), 256>>>(xn, H_DIM, gate_w, H_DIM, nullptr, gate, FF_DIM, H_DIM);
    gemm_nt<<<dim3(44, 32), 256>>>(xn, H_DIM, up_w,   H_DIM, nullptr, up,   FF_DIM, H_DIM);

    // 7) silu(gate) * up -> ff
    {
        int n4 = MROWS * FF_DIM / 4;
        silu_mul_k<<<(n4 + 255) / 256, 256>>>((const float4*)gate, (const float4*)up,
                                              (float4*)ff, n4);
    }

    // 8) down projection + residual -> out
    gemm_nt<<<dim3(16, 32), 256>>>(ff, FF_DIM, down_w, FF_DIM, hbuf, out, H_DIM, FF_DIM);
}

// round 7
// speedup vs baseline: 2.3815x; 2.3815x over previous
#include <cuda_runtime.h>
#include <cstdint>
#include <cstddef>

// Problem constants
#define H_DIM   2048
#define S_LEN   2048
#define B_SZ    2
#define NHEADS  16
#define NKVH    8
#define HD      128
#define FF_DIM  5632
#define MROWS   (B_SZ * S_LEN)          // 4096
#define QKV_LD  4096                    // q(2048) | k(1024) | v(1024)
#define ATT_SCALE 0.08838834764831845f  // 1/sqrt(128)

// ---------------------------------------------------------------------------
// Scratch (allocation is forbidden; __device__ globals are the sanctioned path)
// ---------------------------------------------------------------------------
__device__ float g_xn  [(size_t)MROWS * H_DIM];
__device__ float g_qkv [(size_t)MROWS * QKV_LD];
__device__ float g_attn[(size_t)MROWS * H_DIM];
__device__ float g_h   [(size_t)MROWS * H_DIM];
__device__ float g_gate[(size_t)MROWS * FF_DIM];
__device__ float g_up  [(size_t)MROWS * FF_DIM];
__device__ float g_ff  [(size_t)MROWS * FF_DIM];

// ---------------------------------------------------------------------------
// Helpers (family-portable PTX only: cp.async + mma.sync, no tcgen05)
// ---------------------------------------------------------------------------
__device__ __forceinline__ uint32_t smem_u32(const void* p) {
    uint32_t a;
    asm("{ .reg .u64 t; cvta.to.shared.u64 t, %1; cvt.u32.u64 %0, t; }"
        : "=r"(a) : "l"(p));
    return a;
}

__device__ __forceinline__ uint32_t f2tf32(float x) {
    uint32_t y;
    asm("cvt.rna.tf32.f32 %0, %1;" : "=r"(y) : "f"(x));
    return y;
}

__device__ __forceinline__ void cp_async16(uint32_t dst, const void* src) {
    asm volatile("cp.async.cg.shared.global [%0], [%1], 16;"
                 :: "r"(dst), "l"(src) : "memory");
}
#define CP_COMMIT() asm volatile("cp.async.commit_group;" ::: "memory")
#define CP_WAIT0()  asm volatile("cp.async.wait_group 0;" ::: "memory")

// m16n8k8 tf32 MMA, fp32 accumulate (sm_80+ family-portable)
__device__ __forceinline__ void mma_tf32(float* d, const uint32_t* a, const uint32_t* b) {
    asm volatile(
        "mma.sync.aligned.m16n8k8.row.col.f32.tf32.tf32.f32 "
        "{%0,%1,%2,%3}, {%4,%5,%6,%7}, {%8,%9}, {%0,%1,%2,%3};"
        : "+f"(d[0]), "+f"(d[1]), "+f"(d[2]), "+f"(d[3])
        : "r"(a[0]), "r"(a[1]), "r"(a[2]), "r"(a[3]), "r"(b[0]), "r"(b[1]));
}

// ---------------------------------------------------------------------------
// tf32 tensor-core NT GEMM: C[m,n] = sum_k A[m,k]*B[n,k] (+ optional residual)
// BM=BN=128, BK=32, 256 threads (8 warps, 2x4), warp tile 64x32.
// cp.async double-buffered smem; rows padded to 36 floats (144B) so fragment
// ld.shared is conflict-free (bank = 4g + t4). Grid (N/128, M/128).
// ---------------------------------------------------------------------------
#define RS 36                       // smem row stride in floats (144B)
#define TILE_BYTES (128 * RS * 4)   // 18432 per tile
#define STAGE_BYTES (2 * TILE_BYTES)
#define GEMM_SMEM (2 * STAGE_BYTES) // 73728

__global__ __launch_bounds__(256, 2) void gemm_tc(
    const float* __restrict__ A, int lda,
    const float* __restrict__ B, int ldb,
    const float* __restrict__ Res,
    float* __restrict__ C, int ldc, int K)
{
    extern __shared__ __align__(1024) char sm[];
    const uint32_t sbase = smem_u32(sm);
    const int tid  = threadIdx.x;
    const int wid  = tid >> 5, lane = tid & 31;
    const int g    = lane >> 2, t4 = lane & 3;
    const int wm0  = (wid >> 2) * 64;   // warp M offset in tile
    const int wn0  = (wid & 3) * 32;    // warp N offset in tile
    const int m0   = blockIdx.y * 128;
    const int n0   = blockIdx.x * 128;

    // cp.async source/dest mapping: thread covers rows r0+{0,32,64,96}, seg=tid&7
    const int r0  = tid >> 3;
    const int seg = tid & 7;
    const float* Ab = A + (size_t)(m0 + r0) * lda + seg * 4;
    const float* Bb = B + (size_t)(n0 + r0) * ldb + seg * 4;
    const uint32_t soff = (uint32_t)(r0 * 144 + seg * 16);

    float acc[4][4][4];
    #pragma unroll
    for (int mi = 0; mi < 4; mi++)
        #pragma unroll
        for (int ni = 0; ni < 4; ni++)
            #pragma unroll
            for (int j = 0; j < 4; j++) acc[mi][ni][j] = 0.0f;

    const int NC = K / 32;

    // prologue: load chunk 0 into stage 0
    {
        const uint32_t sA = sbase + soff;
        const uint32_t sB = sA + TILE_BYTES;
        #pragma unroll
        for (int t = 0; t < 4; t++) {
            cp_async16(sA + t * 32 * 144, Ab + (size_t)(t * 32) * lda);
            cp_async16(sB + t * 32 * 144, Bb + (size_t)(t * 32) * ldb);
        }
        CP_COMMIT();
    }

    for (int c = 0; c < NC; c++) {
        CP_WAIT0();
        __syncthreads();

        if (c + 1 < NC) {  // async-load next chunk into the other stage
            const uint32_t sA = sbase + ((c + 1) & 1) * STAGE_BYTES + soff;
            const uint32_t sB = sA + TILE_BYTES;
            const float* An = Ab + (size_t)(c + 1) * 32;
            const float* Bn = Bb + (size_t)(c + 1) * 32;
            #pragma unroll
            for (int t = 0; t < 4; t++) {
                cp_async16(sA + t * 32 * 144, An + (size_t)(t * 32) * lda);
                cp_async16(sB + t * 32 * 144, Bn + (size_t)(t * 32) * ldb);
            }
            CP_COMMIT();
        }

        const float* Asf = (const float*)(sm + (c & 1) * STAGE_BYTES);
        const float* Bsf = Asf + 128 * RS;

        #pragma unroll
        for (int ks = 0; ks < 4; ks++) {
            const int k0 = ks * 8;
            uint32_t ua[4][4], ub[4][2];
            #pragma unroll
            for (int mi = 0; mi < 4; mi++) {
                const float* p = Asf + (wm0 + mi * 16 + g) * RS + k0 + t4;
                ua[mi][0] = f2tf32(p[0]);
                ua[mi][1] = f2tf32(p[8 * RS]);
                ua[mi][2] = f2tf32(p[4]);
                ua[mi][3] = f2tf32(p[8 * RS + 4]);
            }
            #pragma unroll
            for (int ni = 0; ni < 4; ni++) {
                const float* q = Bsf + (wn0 + ni * 8 + g) * RS + k0 + t4;
                ub[ni][0] = f2tf32(q[0]);
                ub[ni][1] = f2tf32(q[4]);
            }
            #pragma unroll
            for (int mi = 0; mi < 4; mi++)
                #pragma unroll
                for (int ni = 0; ni < 4; ni++)
                    mma_tf32(acc[mi][ni], ua[mi], ub[ni]);
        }
        __syncthreads();
    }

    // Epilogue: fragment layout c0,c1=(g, 2t4..2t4+1), c2,c3=(g+8, ...)
    #pragma unroll
    for (int mi = 0; mi < 4; mi++) {
        #pragma unroll
        for (int ni = 0; ni < 4; ni++) {
            const int row = m0 + wm0 + mi * 16 + g;
            const int col = n0 + wn0 + ni * 8 + 2 * t4;
            float2 v0 = make_float2(acc[mi][ni][0], acc[mi][ni][1]);
            float2 v1 = make_float2(acc[mi][ni][2], acc[mi][ni][3]);
            if (Res) {
                float2 e0 = *(const float2*)(Res + (size_t)row * ldc + col);
                float2 e1 = *(const float2*)(Res + (size_t)(row + 8) * ldc + col);
                v0.x += e0.x; v0.y += e0.y;
                v1.x += e1.x; v1.y += e1.y;
            }
            *(float2*)(C + (size_t)row * ldc + col)       = v0;
            *(float2*)(C + (size_t)(row + 8) * ldc + col) = v1;
        }
    }
}

// ---------------------------------------------------------------------------
// RMSNorm: one block per row (H=2048), 256 threads, float4
// ---------------------------------------------------------------------------
__global__ __launch_bounds__(256) void rmsnorm_k(
    const float* __restrict__ x, const float* __restrict__ w, float* __restrict__ y)
{
    const int row = blockIdx.x;
    const float4* xr = (const float4*)(x + (size_t)row * H_DIM);
    float4*       yr = (float4*)(y + (size_t)row * H_DIM);
    const float4* w4 = (const float4*)w;
    const int tid = threadIdx.x;

    float4 v0 = xr[tid];
    float4 v1 = xr[tid + 256];
    float s = v0.x*v0.x + v0.y*v0.y + v0.z*v0.z + v0.w*v0.w
            + v1.x*v1.x + v1.y*v1.y + v1.z*v1.z + v1.w*v1.w;

    #pragma unroll
    for (int off = 16; off; off >>= 1) s += __shfl_xor_sync(0xffffffffu, s, off);

    __shared__ float red[8];
    if ((tid & 31) == 0) red[tid >> 5] = s;
    __syncthreads();
    float tot = red[0] + red[1] + red[2] + red[3] + red[4] + red[5] + red[6] + red[7];
    const float inv = rsqrtf(tot * (1.0f / H_DIM) + 1e-6f);

    float4 w0 = w4[tid], w1 = w4[tid + 256];
    float4 o0, o1;
    o0.x = v0.x * inv * w0.x; o0.y = v0.y * inv * w0.y;
    o0.z = v0.z * inv * w0.z; o0.w = v0.w * inv * w0.w;
    o1.x = v1.x * inv * w1.x; o1.y = v1.y * inv * w1.y;
    o1.z = v1.z * inv * w1.z; o1.w = v1.w * inv * w1.w;
    yr[tid] = o0;
    yr[tid + 256] = o1;
}

// ---------------------------------------------------------------------------
// Causal flash attention, fp32, GQA (kv head = h >> 1). (unchanged)
// ---------------------------------------------------------------------------
#define FLASH_SMEM ((64*128 + 64*132 + 64*128 + 64*64) * 4)

__global__ __launch_bounds__(256) void flash_k(
    const float* __restrict__ qkv, float* __restrict__ out)
{
    extern __shared__ float smf[];
    float* Qs = smf;
    float* Ks = Qs + 64 * 128;
    float* Vs = Ks + 64 * 132;
    float* Ps = Vs + 64 * 128;

    const int qt = gridDim.x - 1 - blockIdx.x;
    const int h  = blockIdx.y;
    const int b  = blockIdx.z;
    const int kvh = h >> 1;
    const int q0 = qt * 64;
    const int tid = threadIdx.x;
    const int tx = tid & 15, ty = tid >> 4;

    const float* qbase = qkv + ((size_t)(b * S_LEN + q0)) * QKV_LD + h * HD;
    const float* kbase = qkv + ((size_t)(b * S_LEN)) * QKV_LD + 2048 + kvh * HD;
    const float* vbase = kbase + 1024;

    #pragma unroll
    for (int t = 0; t < 8; t++) {
        int idx = tid + t * 256;
        int r = idx >> 5;
        int d4 = (idx & 31) << 2;
        float4 v = *(const float4*)(qbase + (size_t)r * QKV_LD + d4);
        v.x *= ATT_SCALE; v.y *= ATT_SCALE; v.z *= ATT_SCALE; v.w *= ATT_SCALE;
        *(float4*)&Qs[r * 128 + d4] = v;
    }

    float m[4], l[4], o[4][8];
    #pragma unroll
    for (int i = 0; i < 4; i++) {
        m[i] = -1e30f; l[i] = 0.0f;
        #pragma unroll
        for (int j = 0; j < 8; j++) o[i][j] = 0.0f;
    }

    for (int kt = 0; kt <= qt; kt++) {
        const int k0 = kt * 64;
        __syncthreads();
        #pragma unroll
        for (int t = 0; t < 8; t++) {
            int idx = tid + t * 256;
            int r = idx >> 5;
            int d4 = (idx & 31) << 2;
            *(float4*)&Ks[r * 132 + d4] = *(const float4*)(kbase + (size_t)(k0 + r) * QKV_LD + d4);
            *(float4*)&Vs[r * 128 + d4] = *(const float4*)(vbase + (size_t)(k0 + r) * QKV_LD + d4);
        }
        __syncthreads();

        float s4[4][4];
        #pragma unroll
        for (int i = 0; i < 4; i++)
            #pragma unroll
            for (int j = 0; j < 4; j++) s4[i][j] = 0.0f;

        const float* qp = &Qs[(ty * 4) * 128];
        const float* kp = &Ks[(tx * 4) * 132];
        #pragma unroll 8
        for (int d = 0; d < 128; d += 4) {
            float4 qv[4], kv[4];
            #pragma unroll
            for (int i = 0; i < 4; i++) qv[i] = *(const float4*)(qp + i * 128 + d);
            #pragma unroll
            for (int j = 0; j < 4; j++) kv[j] = *(const float4*)(kp + j * 132 + d);
            #pragma unroll
            for (int i = 0; i < 4; i++)
                #pragma unroll
                for (int j = 0; j < 4; j++)
                    s4[i][j] += qv[i].x * kv[j].x + qv[i].y * kv[j].y
                              + qv[i].z * kv[j].z + qv[i].w * kv[j].w;
        }

        if (kt == qt) {
            #pragma unroll
            for (int i = 0; i < 4; i++)
                #pragma unroll
                for (int j = 0; j < 4; j++)
                    if (k0 + tx * 4 + j > q0 + ty * 4 + i) s4[i][j] = -1e30f;
        }

        #pragma unroll
        for (int i = 0; i < 4; i++) {
            float tm = fmaxf(fmaxf(s4[i][0], s4[i][1]), fmaxf(s4[i][2], s4[i][3]));
            #pragma unroll
            for (int off = 8; off; off >>= 1)
                tm = fmaxf(tm, __shfl_xor_sync(0xffffffffu, tm, off));
            const float nm = fmaxf(m[i], tm);
            const float alpha = __expf(m[i] - nm);
            m[i] = nm;
            float p0 = __expf(s4[i][0] - nm);
            float p1 = __expf(s4[i][1] - nm);
            float p2 = __expf(s4[i][2] - nm);
            float p3 = __expf(s4[i][3] - nm);
            float rs = p0 + p1 + p2 + p3;
            #pragma unroll
            for (int off = 8; off; off >>= 1)
                rs += __shfl_xor_sync(0xffffffffu, rs, off);
            l[i] = l[i] * alpha + rs;
            #pragma unroll
            for (int j = 0; j < 8; j++) o[i][j] *= alpha;
            *(float4*)&Ps[(ty * 4 + i) * 64 + tx * 4] = make_float4(p0, p1, p2, p3);
        }
        __syncthreads();

        const float* vp = &Vs[tx * 8];
        #pragma unroll 4
        for (int k4 = 0; k4 < 64; k4 += 4) {
            float4 pr[4];
            #pragma unroll
            for (int i = 0; i < 4; i++)
                pr[i] = *(const float4*)&Ps[(ty * 4 + i) * 64 + k4];
            #pragma unroll
            for (int kk = 0; kk < 4; kk++) {
                float4 v0 = *(const float4*)(vp + (size_t)(k4 + kk) * 128);
                float4 v1 = *(const float4*)(vp + (size_t)(k4 + kk) * 128 + 4);
                #pragma unroll
                for (int i = 0; i < 4; i++) {
                    float p = (kk == 0) ? pr[i].x : (kk == 1) ? pr[i].y
                            : (kk == 2) ? pr[i].z : pr[i].w;
                    o[i][0] += p * v0.x; o[i][1] += p * v0.y;
                    o[i][2] += p * v0.z; o[i][3] += p * v0.w;
                    o[i][4] += p * v1.x; o[i][5] += p * v1.y;
                    o[i][6] += p * v1.z; o[i][7] += p * v1.w;
                }
            }
        }
    }

    #pragma unroll
    for (int i = 0; i < 4; i++) {
        const float inv = 1.0f / l[i];
        float* op = out + ((size_t)(b * S_LEN + q0 + ty * 4 + i)) * H_DIM + h * HD + tx * 8;
        *(float4*)op       = make_float4(o[i][0]*inv, o[i][1]*inv, o[i][2]*inv, o[i][3]*inv);
        *(float4*)(op + 4) = make_float4(o[i][4]*inv, o[i][5]*inv, o[i][6]*inv, o[i][7]*inv);
    }
}

// ---------------------------------------------------------------------------
// SiLU(gate) * up, float4 elementwise
// ---------------------------------------------------------------------------
__global__ __launch_bounds__(256) void silu_mul_k(
    const float4* __restrict__ g, const float4* __restrict__ u,
    float4* __restrict__ y, int n4)
{
    int i = blockIdx.x * 256 + threadIdx.x;
    if (i >= n4) return;
    float4 a = g[i], b = u[i], r;
    r.x = a.x / (1.0f + __expf(-a.x)) * b.x;
    r.y = a.y / (1.0f + __expf(-a.y)) * b.y;
    r.z = a.z / (1.0f + __expf(-a.z)) * b.z;
    r.w = a.w / (1.0f + __expf(-a.w)) * b.w;
    y[i] = r;
}

// ---------------------------------------------------------------------------
// Launch
// ---------------------------------------------------------------------------
extern "C" void kernel_launch(void* const* d_in, const int* in_sizes, int n_in,
                              void* d_out, int out_size)
{
    const float* hidden = (const float*)d_in[0];
    const float* q_w    = (const float*)d_in[2];
    const float* k_w    = (const float*)d_in[3];
    const float* v_w    = (const float*)d_in[4];
    const float* o_w    = (const float*)d_in[5];
    const float* gate_w = (const float*)d_in[6];
    const float* up_w   = (const float*)d_in[7];
    const float* down_w = (const float*)d_in[8];
    const float* ln1    = (const float*)d_in[9];
    const float* ln2    = (const float*)d_in[10];
    float* out = (float*)d_out;

    float *xn, *qkv, *attn, *hbuf, *gate, *up, *ff;
    cudaGetSymbolAddress((void**)&xn,   g_xn);
    cudaGetSymbolAddress((void**)&qkv,  g_qkv);
    cudaGetSymbolAddress((void**)&attn, g_attn);
    cudaGetSymbolAddress((void**)&hbuf, g_h);
    cudaGetSymbolAddress((void**)&gate, g_gate);
    cudaGetSymbolAddress((void**)&up,   g_up);
    cudaGetSymbolAddress((void**)&ff,   g_ff);

    cudaFuncSetAttribute(flash_k, cudaFuncAttributeMaxDynamicSharedMemorySize, FLASH_SMEM);
    cudaFuncSetAttribute(gemm_tc, cudaFuncAttributeMaxDynamicSharedMemorySize, GEMM_SMEM);

    // 1) rmsnorm(hidden) -> xn
    rmsnorm_k<<<MROWS, 256>>>(hidden, ln1, xn);

    // 2) QKV projections into fused buffer [row][4096]
    gemm_tc<<<dim3(16, 32), 256, GEMM_SMEM>>>(xn, H_DIM, q_w, H_DIM, nullptr, qkv,        QKV_LD, H_DIM);
    gemm_tc<<<dim3( 8, 32), 256, GEMM_SMEM>>>(xn, H_DIM, k_w, H_DIM, nullptr, qkv + 2048, QKV_LD, H_DIM);
    gemm_tc<<<dim3( 8, 32), 256, GEMM_SMEM>>>(xn, H_DIM, v_w, H_DIM, nullptr, qkv + 3072, QKV_LD, H_DIM);

    // 3) causal flash attention -> attn [row][nh*hd]
    flash_k<<<dim3(S_LEN / 64, NHEADS, B_SZ), 256, FLASH_SMEM>>>(qkv, attn);

    // 4) O projection + residual -> hbuf
    gemm_tc<<<dim3(16, 32), 256, GEMM_SMEM>>>(attn, H_DIM, o_w, H_DIM, hidden, hbuf, H_DIM, H_DIM);

    // 5) rmsnorm(hbuf) -> xn
    rmsnorm_k<<<MROWS, 256>>>(hbuf, ln2, xn);

    // 6) gate/up projections
    gemm_tc<<<dim3(44, 32), 256, GEMM_SMEM>>>(xn, H_DIM, gate_w, H_DIM, nullptr, gate, FF_DIM, H_DIM);
    gemm_tc<<<dim3(44, 32), 256, GEMM_SMEM>>>(xn, H_DIM, up_w,   H_DIM, nullptr, up,   FF_DIM, H_DIM);

    // 7) silu(gate) * up -> ff
    {
        int n4 = MROWS * FF_DIM / 4;
        silu_mul_k<<<(n4 + 255) / 256, 256>>>((const float4*)gate, (const float4*)up,
                                              (float4*)ff, n4);
    }

    // 8) down projection + residual -> out
    gemm_tc<<<dim3(16, 32), 256, GEMM_SMEM>>>(ff, FF_DIM, down_w, FF_DIM, hbuf, out, H_DIM, FF_DIM);
}

// round 8
// speedup vs baseline: 2.6033x; 1.0931x over previous
#include <cuda_runtime.h>
#include <cstdint>
#include <cstddef>

// Problem constants
#define H_DIM   2048
#define S_LEN   2048
#define B_SZ    2
#define NHEADS  16
#define NKVH    8
#define HD      128
#define FF_DIM  5632
#define MROWS   (B_SZ * S_LEN)          // 4096
#define QKV_LD  4096                    // q(2048) | k(1024) | v(1024)
#define ATT_SCALE 0.08838834764831845f  // 1/sqrt(128)

// ---------------------------------------------------------------------------
// Scratch
// ---------------------------------------------------------------------------
__device__ float g_xn  [(size_t)MROWS * H_DIM];
__device__ float g_qkv [(size_t)MROWS * QKV_LD];
__device__ float g_attn[(size_t)MROWS * H_DIM];
__device__ float g_h   [(size_t)MROWS * H_DIM];
__device__ float g_gate[(size_t)MROWS * FF_DIM];
__device__ float g_up  [(size_t)MROWS * FF_DIM];
__device__ float g_ff  [(size_t)MROWS * FF_DIM];
// tf32-rounded weight copies
__device__ float g_wq[(size_t)2048 * 2048];
__device__ float g_wk[(size_t)1024 * 2048];
__device__ float g_wv[(size_t)1024 * 2048];
__device__ float g_wo[(size_t)2048 * 2048];
__device__ float g_wg[(size_t)FF_DIM * 2048];
__device__ float g_wu[(size_t)FF_DIM * 2048];
__device__ float g_wd[(size_t)2048 * FF_DIM];

// ---------------------------------------------------------------------------
// Helpers (family-portable PTX: cp.async + mma.sync + ldmatrix)
// ---------------------------------------------------------------------------
__device__ __forceinline__ uint32_t smem_u32(const void* p) {
    uint32_t a;
    asm("{ .reg .u64 t; cvta.to.shared.u64 t, %1; cvt.u32.u64 %0, t; }"
        : "=r"(a) : "l"(p));
    return a;
}

__device__ __forceinline__ uint32_t f2tf32(float x) {
    uint32_t y;
    asm("cvt.rna.tf32.f32 %0, %1;" : "=r"(y) : "f"(x));
    return y;
}
__device__ __forceinline__ float f2tf32f(float x) {
    return __uint_as_float(f2tf32(x));
}

__device__ __forceinline__ void cp_async16(uint32_t dst, const void* src) {
    asm volatile("cp.async.cg.shared.global [%0], [%1], 16;"
                 :: "r"(dst), "l"(src) : "memory");
}
#define CP_COMMIT() asm volatile("cp.async.commit_group;" ::: "memory")
#define CP_WAIT0()  asm volatile("cp.async.wait_group 0;" ::: "memory")

#define LDSM_X4(r0, r1, r2, r3, addr)                                        \
    asm volatile("ldmatrix.sync.aligned.m8n8.x4.shared.b16 {%0,%1,%2,%3}, [%4];" \
        : "=r"(r0), "=r"(r1), "=r"(r2), "=r"(r3) : "r"(addr))

// m16n8k8 tf32 MMA, fp32 accumulate (sm_80+ family-portable)
__device__ __forceinline__ void mma_tf32(float* d, const uint32_t* a, const uint32_t* b) {
    asm volatile(
        "mma.sync.aligned.m16n8k8.row.col.f32.tf32.tf32.f32 "
        "{%0,%1,%2,%3}, {%4,%5,%6,%7}, {%8,%9}, {%0,%1,%2,%3};"
        : "+f"(d[0]), "+f"(d[1]), "+f"(d[2]), "+f"(d[3])
        : "r"(a[0]), "r"(a[1]), "r"(a[2]), "r"(a[3]), "r"(b[0]), "r"(b[1]));
}

// ---------------------------------------------------------------------------
// Weight pre-round: out[i] = tf32(in[i]) (bit-exact tf32 format in gmem)
// ---------------------------------------------------------------------------
__global__ __launch_bounds__(256) void cvt_w_k(
    const float4* __restrict__ in, float4* __restrict__ out, int n4)
{
    int i = blockIdx.x * 256 + threadIdx.x;
    if (i >= n4) return;
    float4 v = in[i];
    out[i] = make_float4(f2tf32f(v.x), f2tf32f(v.y), f2tf32f(v.z), f2tf32f(v.w));
}

// ---------------------------------------------------------------------------
// tf32 tensor-core NT GEMM: C[m,n] = sum_k A[m,k]*B[n,k] (+ optional residual)
// Inputs MUST be tf32-pre-rounded. BM=BN=128, BK=32, 256 threads (8 warps 2x4),
// warp tile 64x32. cp.async double-buffered; rows padded to 36 floats (144B).
// Fragments fed by ldmatrix.x4 (A: 4/kstep, B: 2/kstep), zero cvt in loop.
// ---------------------------------------------------------------------------
#define RS 36                       // smem row stride in floats (144B)
#define TILE_BYTES (128 * RS * 4)   // 18432 per tile
#define STAGE_BYTES (2 * TILE_BYTES)
#define GEMM_SMEM (2 * STAGE_BYTES) // 73728

__global__ __launch_bounds__(256, 2) void gemm_tc(
    const float* __restrict__ A, int lda,
    const float* __restrict__ B, int ldb,
    const float* __restrict__ Res,
    float* __restrict__ C, int ldc, int K)
{
    extern __shared__ __align__(1024) char sm[];
    const uint32_t sbase = smem_u32(sm);
    const int tid  = threadIdx.x;
    const int wid  = tid >> 5, lane = tid & 31;
    const int g    = lane >> 2, t4 = lane & 3;
    const int wm0  = (wid >> 2) * 64;   // warp M offset in tile
    const int wn0  = (wid & 3) * 32;    // warp N offset in tile
    const int m0   = blockIdx.y * 128;
    const int n0   = blockIdx.x * 128;

    // ldmatrix per-lane byte offsets (relative to stage A/B base).
    // A matrices (per mi): m0 rows+0 k0 | m1 rows+8 k0 | m2 rows+0 k4 | m3 rows+8 k4
    // B matrices (per np): m0 rows+0 k0 | m1 rows+0 k4 | m2 rows+8 k0 | m3 rows+8 k4
    const int j   = lane & 7;
    const int sel = lane >> 3;
    uint32_t offA[4], offB[2];
    #pragma unroll
    for (int mi = 0; mi < 4; mi++)
        offA[mi] = (uint32_t)((wm0 + mi * 16 + (sel & 1) * 8 + j) * 144 + (sel >> 1) * 16);
    #pragma unroll
    for (int np = 0; np < 2; np++)
        offB[np] = (uint32_t)((wn0 + np * 16 + (sel >> 1) * 8 + j) * 144 + (sel & 1) * 16);

    // cp.async mapping: thread covers rows r0+{0,32,64,96}, seg=tid&7
    const int r0  = tid >> 3;
    const int seg = tid & 7;
    const float* Ab = A + (size_t)(m0 + r0) * lda + seg * 4;
    const float* Bb = B + (size_t)(n0 + r0) * ldb + seg * 4;
    const uint32_t soff = (uint32_t)(r0 * 144 + seg * 16);

    float acc[4][4][4];
    #pragma unroll
    for (int mi = 0; mi < 4; mi++)
        #pragma unroll
        for (int ni = 0; ni < 4; ni++)
            #pragma unroll
            for (int jj = 0; jj < 4; jj++) acc[mi][ni][jj] = 0.0f;

    const int NC = K / 32;

    // prologue: chunk 0 -> stage 0
    {
        const uint32_t sA = sbase + soff;
        const uint32_t sB = sA + TILE_BYTES;
        #pragma unroll
        for (int t = 0; t < 4; t++) {
            cp_async16(sA + t * 32 * 144, Ab + (size_t)(t * 32) * lda);
            cp_async16(sB + t * 32 * 144, Bb + (size_t)(t * 32) * ldb);
        }
        CP_COMMIT();
    }

    for (int c = 0; c < NC; c++) {
        CP_WAIT0();
        __syncthreads();

        if (c + 1 < NC) {
            const uint32_t sA = sbase + ((c + 1) & 1) * STAGE_BYTES + soff;
            const uint32_t sB = sA + TILE_BYTES;
            const float* An = Ab + (size_t)(c + 1) * 32;
            const float* Bn = Bb + (size_t)(c + 1) * 32;
            #pragma unroll
            for (int t = 0; t < 4; t++) {
                cp_async16(sA + t * 32 * 144, An + (size_t)(t * 32) * lda);
                cp_async16(sB + t * 32 * 144, Bn + (size_t)(t * 32) * ldb);
            }
            CP_COMMIT();
        }

        const uint32_t stA = sbase + (c & 1) * STAGE_BYTES;
        const uint32_t stB = stA + TILE_BYTES;

        #pragma unroll
        for (int ks = 0; ks < 4; ks++) {
            uint32_t ua[4][4], ub[4][2];
            #pragma unroll
            for (int mi = 0; mi < 4; mi++)
                LDSM_X4(ua[mi][0], ua[mi][1], ua[mi][2], ua[mi][3],
                        stA + offA[mi] + ks * 32);
            #pragma unroll
            for (int np = 0; np < 2; np++)
                LDSM_X4(ub[2*np][0], ub[2*np][1], ub[2*np+1][0], ub[2*np+1][1],
                        stB + offB[np] + ks * 32);
            #pragma unroll
            for (int mi = 0; mi < 4; mi++)
                #pragma unroll
                for (int ni = 0; ni < 4; ni++)
                    mma_tf32(acc[mi][ni], ua[mi], ub[ni]);
        }
        __syncthreads();
    }

    // Epilogue: fragment (c0,c1)=(row g, cols 2t4..2t4+1), (c2,c3)=(row g+8, ...)
    #pragma unroll
    for (int mi = 0; mi < 4; mi++) {
        #pragma unroll
        for (int ni = 0; ni < 4; ni++) {
            const int row = m0 + wm0 + mi * 16 + g;
            const int col = n0 + wn0 + ni * 8 + 2 * t4;
            float2 v0 = make_float2(acc[mi][ni][0], acc[mi][ni][1]);
            float2 v1 = make_float2(acc[mi][ni][2], acc[mi][ni][3]);
            if (Res) {
                float2 e0 = *(const float2*)(Res + (size_t)row * ldc + col);
                float2 e1 = *(const float2*)(Res + (size_t)(row + 8) * ldc + col);
                v0.x += e0.x; v0.y += e0.y;
                v1.x += e1.x; v1.y += e1.y;
            }
            *(float2*)(C + (size_t)row * ldc + col)       = v0;
            *(float2*)(C + (size_t)(row + 8) * ldc + col) = v1;
        }
    }
}

// ---------------------------------------------------------------------------
// RMSNorm: one block per row (H=2048), 256 threads, float4.
// Output tf32-pre-rounded (only consumed by tf32 GEMMs).
// ---------------------------------------------------------------------------
__global__ __launch_bounds__(256) void rmsnorm_k(
    const float* __restrict__ x, const float* __restrict__ w, float* __restrict__ y)
{
    const int row = blockIdx.x;
    const float4* xr = (const float4*)(x + (size_t)row * H_DIM);
    float4*       yr = (float4*)(y + (size_t)row * H_DIM);
    const float4* w4 = (const float4*)w;
    const int tid = threadIdx.x;

    float4 v0 = xr[tid];
    float4 v1 = xr[tid + 256];
    float s = v0.x*v0.x + v0.y*v0.y + v0.z*v0.z + v0.w*v0.w
            + v1.x*v1.x + v1.y*v1.y + v1.z*v1.z + v1.w*v1.w;

    #pragma unroll
    for (int off = 16; off; off >>= 1) s += __shfl_xor_sync(0xffffffffu, s, off);

    __shared__ float red[8];
    if ((tid & 31) == 0) red[tid >> 5] = s;
    __syncthreads();
    float tot = red[0] + red[1] + red[2] + red[3] + red[4] + red[5] + red[6] + red[7];
    const float inv = rsqrtf(tot * (1.0f / H_DIM) + 1e-6f);

    float4 w0 = w4[tid], w1 = w4[tid + 256];
    float4 o0, o1;
    o0.x = f2tf32f(v0.x * inv * w0.x); o0.y = f2tf32f(v0.y * inv * w0.y);
    o0.z = f2tf32f(v0.z * inv * w0.z); o0.w = f2tf32f(v0.w * inv * w0.w);
    o1.x = f2tf32f(v1.x * inv * w1.x); o1.y = f2tf32f(v1.y * inv * w1.y);
    o1.z = f2tf32f(v1.z * inv * w1.z); o1.w = f2tf32f(v1.w * inv * w1.w);
    yr[tid] = o0;
    yr[tid + 256] = o1;
}

// ---------------------------------------------------------------------------
// Causal flash attention, fp32, GQA (kv head = h >> 1).
// Output tf32-pre-rounded (only consumed by O-proj GEMM).
// ---------------------------------------------------------------------------
#define FLASH_SMEM ((64*128 + 64*132 + 64*128 + 64*64) * 4)

__global__ __launch_bounds__(256) void flash_k(
    const float* __restrict__ qkv, float* __restrict__ out)
{
    extern __shared__ float smf[];
    float* Qs = smf;
    float* Ks = Qs + 64 * 128;
    float* Vs = Ks + 64 * 132;
    float* Ps = Vs + 64 * 128;

    const int qt = gridDim.x - 1 - blockIdx.x;
    const int h  = blockIdx.y;
    const int b  = blockIdx.z;
    const int kvh = h >> 1;
    const int q0 = qt * 64;
    const int tid = threadIdx.x;
    const int tx = tid & 15, ty = tid >> 4;

    const float* qbase = qkv + ((size_t)(b * S_LEN + q0)) * QKV_LD + h * HD;
    const float* kbase = qkv + ((size_t)(b * S_LEN)) * QKV_LD + 2048 + kvh * HD;
    const float* vbase = kbase + 1024;

    #pragma unroll
    for (int t = 0; t < 8; t++) {
        int idx = tid + t * 256;
        int r = idx >> 5;
        int d4 = (idx & 31) << 2;
        float4 v = *(const float4*)(qbase + (size_t)r * QKV_LD + d4);
        v.x *= ATT_SCALE; v.y *= ATT_SCALE; v.z *= ATT_SCALE; v.w *= ATT_SCALE;
        *(float4*)&Qs[r * 128 + d4] = v;
    }

    float m[4], l[4], o[4][8];
    #pragma unroll
    for (int i = 0; i < 4; i++) {
        m[i] = -1e30f; l[i] = 0.0f;
        #pragma unroll
        for (int j = 0; j < 8; j++) o[i][j] = 0.0f;
    }

    for (int kt = 0; kt <= qt; kt++) {
        const int k0 = kt * 64;
        __syncthreads();
        #pragma unroll
        for (int t = 0; t < 8; t++) {
            int idx = tid + t * 256;
            int r = idx >> 5;
            int d4 = (idx & 31) << 2;
            *(float4*)&Ks[r * 132 + d4] = *(const float4*)(kbase + (size_t)(k0 + r) * QKV_LD + d4);
            *(float4*)&Vs[r * 128 + d4] = *(const float4*)(vbase + (size_t)(k0 + r) * QKV_LD + d4);
        }
        __syncthreads();

        float s4[4][4];
        #pragma unroll
        for (int i = 0; i < 4; i++)
            #pragma unroll
            for (int j = 0; j < 4; j++) s4[i][j] = 0.0f;

        const float* qp = &Qs[(ty * 4) * 128];
        const float* kp = &Ks[(tx * 4) * 132];
        #pragma unroll 8
        for (int d = 0; d < 128; d += 4) {
            float4 qv[4], kv[4];
            #pragma unroll
            for (int i = 0; i < 4; i++) qv[i] = *(const float4*)(qp + i * 128 + d);
            #pragma unroll
            for (int j = 0; j < 4; j++) kv[j] = *(const float4*)(kp + j * 132 + d);
            #pragma unroll
            for (int i = 0; i < 4; i++)
                #pragma unroll
                for (int j = 0; j < 4; j++)
                    s4[i][j] += qv[i].x * kv[j].x + qv[i].y * kv[j].y
                              + qv[i].z * kv[j].z + qv[i].w * kv[j].w;
        }

        if (kt == qt) {
            #pragma unroll
            for (int i = 0; i < 4; i++)
                #pragma unroll
                for (int j = 0; j < 4; j++)
                    if (k0 + tx * 4 + j > q0 + ty * 4 + i) s4[i][j] = -1e30f;
        }

        #pragma unroll
        for (int i = 0; i < 4; i++) {
            float tm = fmaxf(fmaxf(s4[i][0], s4[i][1]), fmaxf(s4[i][2], s4[i][3]));
            #pragma unroll
            for (int off = 8; off; off >>= 1)
                tm = fmaxf(tm, __shfl_xor_sync(0xffffffffu, tm, off));
            const float nm = fmaxf(m[i], tm);
            const float alpha = __expf(m[i] - nm);
            m[i] = nm;
            float p0 = __expf(s4[i][0] - nm);
            float p1 = __expf(s4[i][1] - nm);
            float p2 = __expf(s4[i][2] - nm);
            float p3 = __expf(s4[i][3] - nm);
            float rs = p0 + p1 + p2 + p3;
            #pragma unroll
            for (int off = 8; off; off >>= 1)
                rs += __shfl_xor_sync(0xffffffffu, rs, off);
            l[i] = l[i] * alpha + rs;
            #pragma unroll
            for (int j = 0; j < 8; j++) o[i][j] *= alpha;
            *(float4*)&Ps[(ty * 4 + i) * 64 + tx * 4] = make_float4(p0, p1, p2, p3);
        }
        __syncthreads();

        const float* vp = &Vs[tx * 8];
        #pragma unroll 4
        for (int k4 = 0; k4 < 64; k4 += 4) {
            float4 pr[4];
            #pragma unroll
            for (int i = 0; i < 4; i++)
                pr[i] = *(const float4*)&Ps[(ty * 4 + i) * 64 + k4];
            #pragma unroll
            for (int kk = 0; kk < 4; kk++) {
                float4 v0 = *(const float4*)(vp + (size_t)(k4 + kk) * 128);
                float4 v1 = *(const float4*)(vp + (size_t)(k4 + kk) * 128 + 4);
                #pragma unroll
                for (int i = 0; i < 4; i++) {
                    float p = (kk == 0) ? pr[i].x : (kk == 1) ? pr[i].y
                            : (kk == 2) ? pr[i].z : pr[i].w;
                    o[i][0] += p * v0.x; o[i][1] += p * v0.y;
                    o[i][2] += p * v0.z; o[i][3] += p * v0.w;
                    o[i][4] += p * v1.x; o[i][5] += p * v1.y;
                    o[i][6] += p * v1.z; o[i][7] += p * v1.w;
                }
            }
        }
    }

    #pragma unroll
    for (int i = 0; i < 4; i++) {
        const float inv = 1.0f / l[i];
        float* op = out + ((size_t)(b * S_LEN + q0 + ty * 4 + i)) * H_DIM + h * HD + tx * 8;
        *(float4*)op = make_float4(f2tf32f(o[i][0]*inv), f2tf32f(o[i][1]*inv),
                                   f2tf32f(o[i][2]*inv), f2tf32f(o[i][3]*inv));
        *(float4*)(op + 4) = make_float4(f2tf32f(o[i][4]*inv), f2tf32f(o[i][5]*inv),
                                         f2tf32f(o[i][6]*inv), f2tf32f(o[i][7]*inv));
    }
}

// ---------------------------------------------------------------------------
// SiLU(gate) * up, float4, output tf32-pre-rounded (feeds down-proj GEMM)
// ---------------------------------------------------------------------------
__global__ __launch_bounds__(256) void silu_mul_k(
    const float4* __restrict__ g, const float4* __restrict__ u,
    float4* __restrict__ y, int n4)
{
    int i = blockIdx.x * 256 + threadIdx.x;
    if (i >= n4) return;
    float4 a = g[i], b = u[i], r;
    r.x = f2tf32f(a.x / (1.0f + __expf(-a.x)) * b.x);
    r.y = f2tf32f(a.y / (1.0f + __expf(-a.y)) * b.y);
    r.z = f2tf32f(a.z / (1.0f + __expf(-a.z)) * b.z);
    r.w = f2tf32f(a.w / (1.0f + __expf(-a.w)) * b.w);
    y[i] = r;
}

// ---------------------------------------------------------------------------
// Launch
// ---------------------------------------------------------------------------
extern "C" void kernel_launch(void* const* d_in, const int* in_sizes, int n_in,
                              void* d_out, int out_size)
{
    const float* hidden = (const float*)d_in[0];
    const float* q_w    = (const float*)d_in[2];
    const float* k_w    = (const float*)d_in[3];
    const float* v_w    = (const float*)d_in[4];
    const float* o_w    = (const float*)d_in[5];
    const float* gate_w = (const float*)d_in[6];
    const float* up_w   = (const float*)d_in[7];
    const float* down_w = (const float*)d_in[8];
    const float* ln1    = (const float*)d_in[9];
    const float* ln2    = (const float*)d_in[10];
    float* out = (float*)d_out;

    float *xn, *qkv, *attn, *hbuf, *gate, *up, *ff;
    float *wq, *wk, *wv, *wo, *wg, *wu, *wd;
    cudaGetSymbolAddress((void**)&xn,   g_xn);
    cudaGetSymbolAddress((void**)&qkv,  g_qkv);
    cudaGetSymbolAddress((void**)&attn, g_attn);
    cudaGetSymbolAddress((void**)&hbuf, g_h);
    cudaGetSymbolAddress((void**)&gate, g_gate);
    cudaGetSymbolAddress((void**)&up,   g_up);
    cudaGetSymbolAddress((void**)&ff,   g_ff);
    cudaGetSymbolAddress((void**)&wq,   g_wq);
    cudaGetSymbolAddress((void**)&wk,   g_wk);
    cudaGetSymbolAddress((void**)&wv,   g_wv);
    cudaGetSymbolAddress((void**)&wo,   g_wo);
    cudaGetSymbolAddress((void**)&wg,   g_wg);
    cudaGetSymbolAddress((void**)&wu,   g_wu);
    cudaGetSymbolAddress((void**)&wd,   g_wd);

    cudaFuncSetAttribute(flash_k, cudaFuncAttributeMaxDynamicSharedMemorySize, FLASH_SMEM);
    cudaFuncSetAttribute(gemm_tc, cudaFuncAttributeMaxDynamicSharedMemorySize, GEMM_SMEM);

    // 0) pre-round weights to tf32 format (idempotent, deterministic)
    {
        auto cvt = [](const float* src, float* dst, size_t n) {
            int n4 = (int)(n / 4);
            cvt_w_k<<<(n4 + 255) / 256, 256>>>((const float4*)src, (float4*)dst, n4);
        };
        cvt(q_w,    wq, (size_t)2048 * 2048);
        cvt(k_w,    wk, (size_t)1024 * 2048);
        cvt(v_w,    wv, (size_t)1024 * 2048);
        cvt(o_w,    wo, (size_t)2048 * 2048);
        cvt(gate_w, wg, (size_t)FF_DIM * 2048);
        cvt(up_w,   wu, (size_t)FF_DIM * 2048);
        cvt(down_w, wd, (size_t)2048 * FF_DIM);
    }

    // 1) rmsnorm(hidden) -> xn (tf32-rounded)
    rmsnorm_k<<<MROWS, 256>>>(hidden, ln1, xn);

    // 2) QKV projections into fused buffer [row][4096]
    gemm_tc<<<dim3(16, 32), 256, GEMM_SMEM>>>(xn, H_DIM, wq, H_DIM, nullptr, qkv,        QKV_LD, H_DIM);
    gemm_tc<<<dim3( 8, 32), 256, GEMM_SMEM>>>(xn, H_DIM, wk, H_DIM, nullptr, qkv + 2048, QKV_LD, H_DIM);
    gemm_tc<<<dim3( 8, 32), 256, GEMM_SMEM>>>(xn, H_DIM, wv, H_DIM, nullptr, qkv + 3072, QKV_LD, H_DIM);

    // 3) causal flash attention -> attn (tf32-rounded)
    flash_k<<<dim3(S_LEN / 64, NHEADS, B_SZ), 256, FLASH_SMEM>>>(qkv, attn);

    // 4) O projection + residual -> hbuf
    gemm_tc<<<dim3(16, 32), 256, GEMM_SMEM>>>(attn, H_DIM, wo, H_DIM, hidden, hbuf, H_DIM, H_DIM);

    // 5) rmsnorm(hbuf) -> xn (tf32-rounded)
    rmsnorm_k<<<MROWS, 256>>>(hbuf, ln2, xn);

    // 6) gate/up projections
    gemm_tc<<<dim3(44, 32), 256, GEMM_SMEM>>>(xn, H_DIM, wg, H_DIM, nullptr, gate, FF_DIM, H_DIM);
    gemm_tc<<<dim3(44, 32), 256, GEMM_SMEM>>>(xn, H_DIM, wu, H_DIM, nullptr, up,   FF_DIM, H_DIM);

    // 7) silu(gate) * up -> ff (tf32-rounded)
    {
        int n4 = MROWS * FF_DIM / 4;
        silu_mul_k<<<(n4 + 255) / 256, 256>>>((const float4*)gate, (const float4*)up,
                                              (float4*)ff, n4);
    }

    // 8) down projection + residual -> out
    gemm_tc<<<dim3(16, 32), 256, GEMM_SMEM>>>(ff, FF_DIM, wd, FF_DIM, hbuf, out, H_DIM, FF_DIM);
}

// round 9
// speedup vs baseline: 3.9114x; 1.5025x over previous
#include <cuda_runtime.h>
#include <cstdint>
#include <cstddef>

// Problem constants
#define H_DIM   2048
#define S_LEN   2048
#define B_SZ    2
#define NHEADS  16
#define NKVH    8
#define HD      128
#define FF_DIM  5632
#define MROWS   (B_SZ * S_LEN)          // 4096
#define QKV_LD  4096                    // q(2048) | k(1024) | v(1024)
#define ATT_SCALE 0.08838834764831845f  // 1/sqrt(128)

// ---------------------------------------------------------------------------
// Scratch
// ---------------------------------------------------------------------------
__device__ float g_xn  [(size_t)MROWS * H_DIM];
__device__ float g_qkv [(size_t)MROWS * QKV_LD];
__device__ float g_attn[(size_t)MROWS * H_DIM];
__device__ float g_h   [(size_t)MROWS * H_DIM];
__device__ float g_gate[(size_t)MROWS * FF_DIM];
__device__ float g_up  [(size_t)MROWS * FF_DIM];
__device__ float g_ff  [(size_t)MROWS * FF_DIM];
// tf32-rounded weight copies
__device__ float g_wq[(size_t)2048 * 2048];
__device__ float g_wk[(size_t)1024 * 2048];
__device__ float g_wv[(size_t)1024 * 2048];
__device__ float g_wo[(size_t)2048 * 2048];
__device__ float g_wg[(size_t)FF_DIM * 2048];
__device__ float g_wu[(size_t)FF_DIM * 2048];
__device__ float g_wd[(size_t)2048 * FF_DIM];

// ---------------------------------------------------------------------------
// Helpers (family-portable PTX: cp.async + mma.sync + ldmatrix)
// ---------------------------------------------------------------------------
__device__ __forceinline__ uint32_t smem_u32(const void* p) {
    uint32_t a;
    asm("{ .reg .u64 t; cvta.to.shared.u64 t, %1; cvt.u32.u64 %0, t; }"
        : "=r"(a) : "l"(p));
    return a;
}

__device__ __forceinline__ uint32_t f2tf32(float x) {
    uint32_t y;
    asm("cvt.rna.tf32.f32 %0, %1;" : "=r"(y) : "f"(x));
    return y;
}
__device__ __forceinline__ float f2tf32f(float x) {
    return __uint_as_float(f2tf32(x));
}

__device__ __forceinline__ void cp_async16(uint32_t dst, const void* src) {
    asm volatile("cp.async.cg.shared.global [%0], [%1], 16;"
                 :: "r"(dst), "l"(src) : "memory");
}
#define CP_COMMIT() asm volatile("cp.async.commit_group;" ::: "memory")
#define CP_WAIT0()  asm volatile("cp.async.wait_group 0;" ::: "memory")

#define LDSM_X4(r0, r1, r2, r3, addr)                                        \
    asm volatile("ldmatrix.sync.aligned.m8n8.x4.shared.b16 {%0,%1,%2,%3}, [%4];" \
        : "=r"(r0), "=r"(r1), "=r"(r2), "=r"(r3) : "r"(addr))

// m16n8k8 tf32 MMA, fp32 accumulate (sm_80+ family-portable)
__device__ __forceinline__ void mma_tf32(float* d, const uint32_t* a, const uint32_t* b) {
    asm volatile(
        "mma.sync.aligned.m16n8k8.row.col.f32.tf32.tf32.f32 "
        "{%0,%1,%2,%3}, {%4,%5,%6,%7}, {%8,%9}, {%0,%1,%2,%3};"
        : "+f"(d[0]), "+f"(d[1]), "+f"(d[2]), "+f"(d[3])
        : "r"(a[0]), "r"(a[1]), "r"(a[2]), "r"(a[3]), "r"(b[0]), "r"(b[1]));
}

// ---------------------------------------------------------------------------
// Weight pre-round: out[i] = tf32(in[i])
// ---------------------------------------------------------------------------
__global__ __launch_bounds__(256) void cvt_w_k(
    const float4* __restrict__ in, float4* __restrict__ out, int n4)
{
    int i = blockIdx.x * 256 + threadIdx.x;
    if (i >= n4) return;
    float4 v = in[i];
    out[i] = make_float4(f2tf32f(v.x), f2tf32f(v.y), f2tf32f(v.z), f2tf32f(v.w));
}

// ---------------------------------------------------------------------------
// tf32 tensor-core NT GEMM (unchanged from R7/R8)
// ---------------------------------------------------------------------------
#define RS 36
#define TILE_BYTES (128 * RS * 4)
#define STAGE_BYTES (2 * TILE_BYTES)
#define GEMM_SMEM (2 * STAGE_BYTES)

__global__ __launch_bounds__(256, 2) void gemm_tc(
    const float* __restrict__ A, int lda,
    const float* __restrict__ B, int ldb,
    const float* __restrict__ Res,
    float* __restrict__ C, int ldc, int K)
{
    extern __shared__ __align__(1024) char sm[];
    const uint32_t sbase = smem_u32(sm);
    const int tid  = threadIdx.x;
    const int wid  = tid >> 5, lane = tid & 31;
    const int g    = lane >> 2, t4 = lane & 3;
    const int wm0  = (wid >> 2) * 64;
    const int wn0  = (wid & 3) * 32;
    const int m0   = blockIdx.y * 128;
    const int n0   = blockIdx.x * 128;

    const int j   = lane & 7;
    const int sel = lane >> 3;
    uint32_t offA[4], offB[2];
    #pragma unroll
    for (int mi = 0; mi < 4; mi++)
        offA[mi] = (uint32_t)((wm0 + mi * 16 + (sel & 1) * 8 + j) * 144 + (sel >> 1) * 16);
    #pragma unroll
    for (int np = 0; np < 2; np++)
        offB[np] = (uint32_t)((wn0 + np * 16 + (sel >> 1) * 8 + j) * 144 + (sel & 1) * 16);

    const int r0  = tid >> 3;
    const int seg = tid & 7;
    const float* Ab = A + (size_t)(m0 + r0) * lda + seg * 4;
    const float* Bb = B + (size_t)(n0 + r0) * ldb + seg * 4;
    const uint32_t soff = (uint32_t)(r0 * 144 + seg * 16);

    float acc[4][4][4];
    #pragma unroll
    for (int mi = 0; mi < 4; mi++)
        #pragma unroll
        for (int ni = 0; ni < 4; ni++)
            #pragma unroll
            for (int jj = 0; jj < 4; jj++) acc[mi][ni][jj] = 0.0f;

    const int NC = K / 32;

    {
        const uint32_t sA = sbase + soff;
        const uint32_t sB = sA + TILE_BYTES;
        #pragma unroll
        for (int t = 0; t < 4; t++) {
            cp_async16(sA + t * 32 * 144, Ab + (size_t)(t * 32) * lda);
            cp_async16(sB + t * 32 * 144, Bb + (size_t)(t * 32) * ldb);
        }
        CP_COMMIT();
    }

    for (int c = 0; c < NC; c++) {
        CP_WAIT0();
        __syncthreads();

        if (c + 1 < NC) {
            const uint32_t sA = sbase + ((c + 1) & 1) * STAGE_BYTES + soff;
            const uint32_t sB = sA + TILE_BYTES;
            const float* An = Ab + (size_t)(c + 1) * 32;
            const float* Bn = Bb + (size_t)(c + 1) * 32;
            #pragma unroll
            for (int t = 0; t < 4; t++) {
                cp_async16(sA + t * 32 * 144, An + (size_t)(t * 32) * lda);
                cp_async16(sB + t * 32 * 144, Bn + (size_t)(t * 32) * ldb);
            }
            CP_COMMIT();
        }

        const uint32_t stA = sbase + (c & 1) * STAGE_BYTES;
        const uint32_t stB = stA + TILE_BYTES;

        #pragma unroll
        for (int ks = 0; ks < 4; ks++) {
            uint32_t ua[4][4], ub[4][2];
            #pragma unroll
            for (int mi = 0; mi < 4; mi++)
                LDSM_X4(ua[mi][0], ua[mi][1], ua[mi][2], ua[mi][3],
                        stA + offA[mi] + ks * 32);
            #pragma unroll
            for (int np = 0; np < 2; np++)
                LDSM_X4(ub[2*np][0], ub[2*np][1], ub[2*np+1][0], ub[2*np+1][1],
                        stB + offB[np] + ks * 32);
            #pragma unroll
            for (int mi = 0; mi < 4; mi++)
                #pragma unroll
                for (int ni = 0; ni < 4; ni++)
                    mma_tf32(acc[mi][ni], ua[mi], ub[ni]);
        }
        __syncthreads();
    }

    #pragma unroll
    for (int mi = 0; mi < 4; mi++) {
        #pragma unroll
        for (int ni = 0; ni < 4; ni++) {
            const int row = m0 + wm0 + mi * 16 + g;
            const int col = n0 + wn0 + ni * 8 + 2 * t4;
            float2 v0 = make_float2(acc[mi][ni][0], acc[mi][ni][1]);
            float2 v1 = make_float2(acc[mi][ni][2], acc[mi][ni][3]);
            if (Res) {
                float2 e0 = *(const float2*)(Res + (size_t)row * ldc + col);
                float2 e1 = *(const float2*)(Res + (size_t)(row + 8) * ldc + col);
                v0.x += e0.x; v0.y += e0.y;
                v1.x += e1.x; v1.y += e1.y;
            }
            *(float2*)(C + (size_t)row * ldc + col)       = v0;
            *(float2*)(C + (size_t)(row + 8) * ldc + col) = v1;
        }
    }
}

// ---------------------------------------------------------------------------
// RMSNorm (tf32-rounded output)
// ---------------------------------------------------------------------------
__global__ __launch_bounds__(256) void rmsnorm_k(
    const float* __restrict__ x, const float* __restrict__ w, float* __restrict__ y)
{
    const int row = blockIdx.x;
    const float4* xr = (const float4*)(x + (size_t)row * H_DIM);
    float4*       yr = (float4*)(y + (size_t)row * H_DIM);
    const float4* w4 = (const float4*)w;
    const int tid = threadIdx.x;

    float4 v0 = xr[tid];
    float4 v1 = xr[tid + 256];
    float s = v0.x*v0.x + v0.y*v0.y + v0.z*v0.z + v0.w*v0.w
            + v1.x*v1.x + v1.y*v1.y + v1.z*v1.z + v1.w*v1.w;

    #pragma unroll
    for (int off = 16; off; off >>= 1) s += __shfl_xor_sync(0xffffffffu, s, off);

    __shared__ float red[8];
    if ((tid & 31) == 0) red[tid >> 5] = s;
    __syncthreads();
    float tot = red[0] + red[1] + red[2] + red[3] + red[4] + red[5] + red[6] + red[7];
    const float inv = rsqrtf(tot * (1.0f / H_DIM) + 1e-6f);

    float4 w0 = w4[tid], w1 = w4[tid + 256];
    float4 o0, o1;
    o0.x = f2tf32f(v0.x * inv * w0.x); o0.y = f2tf32f(v0.y * inv * w0.y);
    o0.z = f2tf32f(v0.z * inv * w0.z); o0.w = f2tf32f(v0.w * inv * w0.w);
    o1.x = f2tf32f(v1.x * inv * w1.x); o1.y = f2tf32f(v1.y * inv * w1.y);
    o1.z = f2tf32f(v1.z * inv * w1.z); o1.w = f2tf32f(v1.w * inv * w1.w);
    yr[tid] = o0;
    yr[tid + 256] = o1;
}

// ---------------------------------------------------------------------------
// Tensor-core causal flash attention (tf32 mma), GQA kvh = h>>1.
// CTA: 128 q-rows, 64 k-rows per tile. 8 warps; warp w owns q-rows [16w,16w+16).
// QK^T: A=Q[128x128] (pitch 132f), B=K[64x128] (pitch 132f) -- NT fragments.
// PV:   A=P[128x64]  (pitch 68f),  B=V^T[128x64] (pitch 68f) -- NT fragments.
// Softmax fp32 in fragment registers; quad-row reduce via shfl_xor 1,2.
// ---------------------------------------------------------------------------
#define QP 132
#define VP 68
#define FLASH_SMEM ((128*QP + 64*QP + 128*VP + 128*VP) * 4)   // 171008

__global__ __launch_bounds__(256, 1) void flash_tc(
    const float* __restrict__ qkv, float* __restrict__ out)
{
    extern __shared__ float smf[];
    float* Qs  = smf;                  // [128][132]
    float* Ks  = Qs + 128 * QP;        // [64][132]
    float* Vts = Ks + 64 * QP;         // [128][68]  d-major (transposed V)
    float* Ps  = Vts + 128 * VP;       // [128][68]

    const int qt = gridDim.x - 1 - blockIdx.x;   // descending qt: causal balance
    const int h  = blockIdx.y;
    const int b  = blockIdx.z;
    const int kvh = h >> 1;
    const int q0 = qt * 128;
    const int tid = threadIdx.x;
    const int wid = tid >> 5, lane = tid & 31;
    const int g = lane >> 2, t4 = lane & 3;
    const int j = lane & 7, sel = lane >> 3;
    const int wm0 = wid * 16;

    const float* qbase = qkv + ((size_t)(b * S_LEN + q0)) * QKV_LD + h * HD;
    const float* kbase = qkv + ((size_t)(b * S_LEN)) * QKV_LD + 2048 + kvh * HD;
    const float* vbase = kbase + 1024;

    // Load Q tile: scale by 1/sqrt(HD), round to tf32
    #pragma unroll
    for (int t = 0; t < 16; t++) {
        int idx = tid + t * 256;
        int r = idx >> 5;
        int c4 = (idx & 31) << 2;
        float4 v = *(const float4*)(qbase + (size_t)r * QKV_LD + c4);
        v.x = f2tf32f(v.x * ATT_SCALE); v.y = f2tf32f(v.y * ATT_SCALE);
        v.z = f2tf32f(v.z * ATT_SCALE); v.w = f2tf32f(v.w * ATT_SCALE);
        *(float4*)&Qs[r * QP + c4] = v;
    }

    const uint32_t sQ = smem_u32(Qs), sK = smem_u32(Ks);
    const uint32_t sV = smem_u32(Vts), sP = smem_u32(Ps);

    // ldmatrix lane byte-offsets (NT fragment mapping, validated in gemm_tc)
    const uint32_t offQA = (uint32_t)((wm0 + (sel & 1) * 8 + j) * (QP * 4) + (sel >> 1) * 16);
    uint32_t offKB[4];
    #pragma unroll
    for (int np = 0; np < 4; np++)
        offKB[np] = (uint32_t)((np * 16 + (sel >> 1) * 8 + j) * (QP * 4) + (sel & 1) * 16);
    const uint32_t offPA = (uint32_t)((wm0 + (sel & 1) * 8 + j) * (VP * 4) + (sel >> 1) * 16);
    uint32_t offVB[8];
    #pragma unroll
    for (int np = 0; np < 8; np++)
        offVB[np] = (uint32_t)((np * 16 + (sel >> 1) * 8 + j) * (VP * 4) + (sel & 1) * 16);

    float m0 = -1e30f, m1 = -1e30f, l0 = 0.0f, l1 = 0.0f;
    float o[16][4];
    #pragma unroll
    for (int nt = 0; nt < 16; nt++)
        #pragma unroll
        for (int c = 0; c < 4; c++) o[nt][c] = 0.0f;

    const int nkt = 2 * qt + 2;
    for (int kt = 0; kt < nkt; kt++) {
        const int k0 = kt * 64;
        __syncthreads();   // protect Ks/Vts reuse across iterations

        // Load K and V^T tiles (tf32-rounded)
        #pragma unroll
        for (int t = 0; t < 8; t++) {
            int idx = tid + t * 256;
            int r = idx >> 5;
            int c4 = (idx & 31) << 2;
            float4 kv = *(const float4*)(kbase + (size_t)(k0 + r) * QKV_LD + c4);
            kv.x = f2tf32f(kv.x); kv.y = f2tf32f(kv.y);
            kv.z = f2tf32f(kv.z); kv.w = f2tf32f(kv.w);
            *(float4*)&Ks[r * QP + c4] = kv;
            float4 vv = *(const float4*)(vbase + (size_t)(k0 + r) * QKV_LD + c4);
            Vts[(c4 + 0) * VP + r] = f2tf32f(vv.x);
            Vts[(c4 + 1) * VP + r] = f2tf32f(vv.y);
            Vts[(c4 + 2) * VP + r] = f2tf32f(vv.z);
            Vts[(c4 + 3) * VP + r] = f2tf32f(vv.w);
        }
        __syncthreads();

        // --- S = Q K^T (warp: 16 q-rows x 64 k-cols) ---
        float s[8][4];
        #pragma unroll
        for (int nt = 0; nt < 8; nt++)
            #pragma unroll
            for (int c = 0; c < 4; c++) s[nt][c] = 0.0f;

        #pragma unroll
        for (int ks = 0; ks < 16; ks++) {
            uint32_t a[4], bb[8][2];
            LDSM_X4(a[0], a[1], a[2], a[3], sQ + offQA + ks * 32);
            #pragma unroll
            for (int np = 0; np < 4; np++)
                LDSM_X4(bb[2*np][0], bb[2*np][1], bb[2*np+1][0], bb[2*np+1][1],
                        sK + offKB[np] + ks * 32);
            #pragma unroll
            for (int nt = 0; nt < 8; nt++)
                mma_tf32(s[nt], a, bb[nt]);
        }

        // --- causal mask (only possible on the last two k-tiles) ---
        if (kt >= 2 * qt) {
            const int r0g = q0 + wm0 + g;
            const int r1g = r0g + 8;
            #pragma unroll
            for (int nt = 0; nt < 8; nt++) {
                const int c0 = k0 + nt * 8 + 2 * t4;
                const int c1 = c0 + 1;
                if (c0 > r0g) s[nt][0] = -1e30f;
                if (c1 > r0g) s[nt][1] = -1e30f;
                if (c0 > r1g) s[nt][2] = -1e30f;
                if (c1 > r1g) s[nt][3] = -1e30f;
            }
        }

        // --- online softmax (rows g and g+8 of this warp's 16) ---
        float mx0 = -1e30f, mx1 = -1e30f;
        #pragma unroll
        for (int nt = 0; nt < 8; nt++) {
            mx0 = fmaxf(mx0, fmaxf(s[nt][0], s[nt][1]));
            mx1 = fmaxf(mx1, fmaxf(s[nt][2], s[nt][3]));
        }
        mx0 = fmaxf(mx0, __shfl_xor_sync(0xffffffffu, mx0, 1));
        mx0 = fmaxf(mx0, __shfl_xor_sync(0xffffffffu, mx0, 2));
        mx1 = fmaxf(mx1, __shfl_xor_sync(0xffffffffu, mx1, 1));
        mx1 = fmaxf(mx1, __shfl_xor_sync(0xffffffffu, mx1, 2));

        const float nm0 = fmaxf(m0, mx0);
        const float nm1 = fmaxf(m1, mx1);
        const float al0 = __expf(m0 - nm0);
        const float al1 = __expf(m1 - nm1);
        m0 = nm0; m1 = nm1;

        float rs0 = 0.0f, rs1 = 0.0f;
        const int prow0 = (wm0 + g) * VP + 2 * t4;
        const int prow1 = (wm0 + g + 8) * VP + 2 * t4;
        #pragma unroll
        for (int nt = 0; nt < 8; nt++) {
            float p0 = __expf(s[nt][0] - nm0);
            float p1 = __expf(s[nt][1] - nm0);
            float p2 = __expf(s[nt][2] - nm1);
            float p3 = __expf(s[nt][3] - nm1);
            rs0 += p0 + p1;
            rs1 += p2 + p3;
            *(float2*)&Ps[prow0 + nt * 8] = make_float2(f2tf32f(p0), f2tf32f(p1));
            *(float2*)&Ps[prow1 + nt * 8] = make_float2(f2tf32f(p2), f2tf32f(p3));
        }
        rs0 += __shfl_xor_sync(0xffffffffu, rs0, 1);
        rs0 += __shfl_xor_sync(0xffffffffu, rs0, 2);
        rs1 += __shfl_xor_sync(0xffffffffu, rs1, 1);
        rs1 += __shfl_xor_sync(0xffffffffu, rs1, 2);
        l0 = l0 * al0 + rs0;
        l1 = l1 * al1 + rs1;

        #pragma unroll
        for (int nt = 0; nt < 16; nt++) {
            o[nt][0] *= al0; o[nt][1] *= al0;
            o[nt][2] *= al1; o[nt][3] *= al1;
        }
        __syncwarp();   // order Ps stores before ldmatrix (warp-private rows)

        // --- O += P V  (warp: 16 q-rows x 128 d-cols) ---
        #pragma unroll
        for (int ks = 0; ks < 8; ks++) {
            uint32_t pa[4], vb[16][2];
            LDSM_X4(pa[0], pa[1], pa[2], pa[3], sP + offPA + ks * 32);
            #pragma unroll
            for (int np = 0; np < 8; np++)
                LDSM_X4(vb[2*np][0], vb[2*np][1], vb[2*np+1][0], vb[2*np+1][1],
                        sV + offVB[np] + ks * 32);
            #pragma unroll
            for (int nt = 0; nt < 16; nt++)
                mma_tf32(o[nt], pa, vb[nt]);
        }
    }

    // --- normalize and write (tf32-rounded; feeds O-proj GEMM) ---
    const float inv0 = 1.0f / l0;
    const float inv1 = 1.0f / l1;
    const size_t row0 = (size_t)(b * S_LEN + q0 + wm0 + g);
    #pragma unroll
    for (int nt = 0; nt < 16; nt++) {
        const int col = h * HD + nt * 8 + 2 * t4;
        *(float2*)(out + row0 * H_DIM + col) =
            make_float2(f2tf32f(o[nt][0] * inv0), f2tf32f(o[nt][1] * inv0));
        *(float2*)(out + (row0 + 8) * H_DIM + col) =
            make_float2(f2tf32f(o[nt][2] * inv1), f2tf32f(o[nt][3] * inv1));
    }
}

// ---------------------------------------------------------------------------
// SiLU(gate) * up, float4, tf32-rounded output
// ---------------------------------------------------------------------------
__global__ __launch_bounds__(256) void silu_mul_k(
    const float4* __restrict__ g, const float4* __restrict__ u,
    float4* __restrict__ y, int n4)
{
    int i = blockIdx.x * 256 + threadIdx.x;
    if (i >= n4) return;
    float4 a = g[i], b = u[i], r;
    r.x = f2tf32f(a.x / (1.0f + __expf(-a.x)) * b.x);
    r.y = f2tf32f(a.y / (1.0f + __expf(-a.y)) * b.y);
    r.z = f2tf32f(a.z / (1.0f + __expf(-a.z)) * b.z);
    r.w = f2tf32f(a.w / (1.0f + __expf(-a.w)) * b.w);
    y[i] = r;
}

// ---------------------------------------------------------------------------
// Launch
// ---------------------------------------------------------------------------
extern "C" void kernel_launch(void* const* d_in, const int* in_sizes, int n_in,
                              void* d_out, int out_size)
{
    const float* hidden = (const float*)d_in[0];
    const float* q_w    = (const float*)d_in[2];
    const float* k_w    = (const float*)d_in[3];
    const float* v_w    = (const float*)d_in[4];
    const float* o_w    = (const float*)d_in[5];
    const float* gate_w = (const float*)d_in[6];
    const float* up_w   = (const float*)d_in[7];
    const float* down_w = (const float*)d_in[8];
    const float* ln1    = (const float*)d_in[9];
    const float* ln2    = (const float*)d_in[10];
    float* out = (float*)d_out;

    float *xn, *qkv, *attn, *hbuf, *gate, *up, *ff;
    float *wq, *wk, *wv, *wo, *wg, *wu, *wd;
    cudaGetSymbolAddress((void**)&xn,   g_xn);
    cudaGetSymbolAddress((void**)&qkv,  g_qkv);
    cudaGetSymbolAddress((void**)&attn, g_attn);
    cudaGetSymbolAddress((void**)&hbuf, g_h);
    cudaGetSymbolAddress((void**)&gate, g_gate);
    cudaGetSymbolAddress((void**)&up,   g_up);
    cudaGetSymbolAddress((void**)&ff,   g_ff);
    cudaGetSymbolAddress((void**)&wq,   g_wq);
    cudaGetSymbolAddress((void**)&wk,   g_wk);
    cudaGetSymbolAddress((void**)&wv,   g_wv);
    cudaGetSymbolAddress((void**)&wo,   g_wo);
    cudaGetSymbolAddress((void**)&wg,   g_wg);
    cudaGetSymbolAddress((void**)&wu,   g_wu);
    cudaGetSymbolAddress((void**)&wd,   g_wd);

    cudaFuncSetAttribute(flash_tc, cudaFuncAttributeMaxDynamicSharedMemorySize, FLASH_SMEM);
    cudaFuncSetAttribute(gemm_tc,  cudaFuncAttributeMaxDynamicSharedMemorySize, GEMM_SMEM);

    // 0) pre-round weights to tf32 format
    {
        auto cvt = [](const float* src, float* dst, size_t n) {
            int n4 = (int)(n / 4);
            cvt_w_k<<<(n4 + 255) / 256, 256>>>((const float4*)src, (float4*)dst, n4);
        };
        cvt(q_w,    wq, (size_t)2048 * 2048);
        cvt(k_w,    wk, (size_t)1024 * 2048);
        cvt(v_w,    wv, (size_t)1024 * 2048);
        cvt(o_w,    wo, (size_t)2048 * 2048);
        cvt(gate_w, wg, (size_t)FF_DIM * 2048);
        cvt(up_w,   wu, (size_t)FF_DIM * 2048);
        cvt(down_w, wd, (size_t)2048 * FF_DIM);
    }

    // 1) rmsnorm(hidden) -> xn (tf32-rounded)
    rmsnorm_k<<<MROWS, 256>>>(hidden, ln1, xn);

    // 2) QKV projections into fused buffer [row][4096]
    gemm_tc<<<dim3(16, 32), 256, GEMM_SMEM>>>(xn, H_DIM, wq, H_DIM, nullptr, qkv,        QKV_LD, H_DIM);
    gemm_tc<<<dim3( 8, 32), 256, GEMM_SMEM>>>(xn, H_DIM, wk, H_DIM, nullptr, qkv + 2048, QKV_LD, H_DIM);
    gemm_tc<<<dim3( 8, 32), 256, GEMM_SMEM>>>(xn, H_DIM, wv, H_DIM, nullptr, qkv + 3072, QKV_LD, H_DIM);

    // 3) tensor-core causal flash attention -> attn (tf32-rounded)
    flash_tc<<<dim3(S_LEN / 128, NHEADS, B_SZ), 256, FLASH_SMEM>>>(qkv, attn);

    // 4) O projection + residual -> hbuf
    gemm_tc<<<dim3(16, 32), 256, GEMM_SMEM>>>(attn, H_DIM, wo, H_DIM, hidden, hbuf, H_DIM, H_DIM);

    // 5) rmsnorm(hbuf) -> xn (tf32-rounded)
    rmsnorm_k<<<MROWS, 256>>>(hbuf, ln2, xn);

    // 6) gate/up projections
    gemm_tc<<<dim3(44, 32), 256, GEMM_SMEM>>>(xn, H_DIM, wg, H_DIM, nullptr, gate, FF_DIM, H_DIM);
    gemm_tc<<<dim3(44, 32), 256, GEMM_SMEM>>>(xn, H_DIM, wu, H_DIM, nullptr, up,   FF_DIM, H_DIM);

    // 7) silu(gate) * up -> ff (tf32-rounded)
    {
        int n4 = MROWS * FF_DIM / 4;
        silu_mul_k<<<(n4 + 255) / 256, 256>>>((const float4*)gate, (const float4*)up,
                                              (float4*)ff, n4);
    }

    // 8) down projection + residual -> out
    gemm_tc<<<dim3(16, 32), 256, GEMM_SMEM>>>(ff, FF_DIM, wd, FF_DIM, hbuf, out, H_DIM, FF_DIM);
}

// round 10
// speedup vs baseline: 3.9924x; 1.0207x over previous
#include <cuda_runtime.h>
#include <cstdint>
#include <cstddef>

// Problem constants
#define H_DIM   2048
#define S_LEN   2048
#define B_SZ    2
#define NHEADS  16
#define NKVH    8
#define HD      128
#define FF_DIM  5632
#define MROWS   (B_SZ * S_LEN)          // 4096
#define QKV_LD  4096                    // q(2048) | k(1024) | v(1024)
#define ATT_SCALE 0.08838834764831845f  // 1/sqrt(128)

// ---------------------------------------------------------------------------
// Scratch
// ---------------------------------------------------------------------------
__device__ float g_xn  [(size_t)MROWS * H_DIM];
__device__ float g_qkv [(size_t)MROWS * QKV_LD];
__device__ float g_attn[(size_t)MROWS * H_DIM];
__device__ float g_h   [(size_t)MROWS * H_DIM];
__device__ float g_gate[(size_t)MROWS * FF_DIM];
__device__ float g_ff  [(size_t)MROWS * FF_DIM];
// tf32-rounded weight copies
__device__ float g_wqkv[(size_t)4096 * 2048];    // [q(2048) ; k(1024) ; v(1024)] rows
__device__ float g_wo[(size_t)2048 * 2048];
__device__ float g_wg[(size_t)FF_DIM * 2048];
__device__ float g_wu[(size_t)FF_DIM * 2048];
__device__ float g_wd[(size_t)2048 * FF_DIM];

// ---------------------------------------------------------------------------
// Helpers (family-portable PTX: cp.async + mma.sync + ldmatrix)
// ---------------------------------------------------------------------------
__device__ __forceinline__ uint32_t smem_u32(const void* p) {
    uint32_t a;
    asm("{ .reg .u64 t; cvta.to.shared.u64 t, %1; cvt.u32.u64 %0, t; }"
        : "=r"(a) : "l"(p));
    return a;
}

__device__ __forceinline__ uint32_t f2tf32(float x) {
    uint32_t y;
    asm("cvt.rna.tf32.f32 %0, %1;" : "=r"(y) : "f"(x));
    return y;
}
__device__ __forceinline__ float f2tf32f(float x) {
    return __uint_as_float(f2tf32(x));
}

__device__ __forceinline__ void cp_async16(uint32_t dst, const void* src) {
    asm volatile("cp.async.cg.shared.global [%0], [%1], 16;"
                 :: "r"(dst), "l"(src) : "memory");
}
#define CP_COMMIT() asm volatile("cp.async.commit_group;" ::: "memory")
#define CP_WAIT0()  asm volatile("cp.async.wait_group 0;" ::: "memory")

#define LDSM_X4(r0, r1, r2, r3, addr)                                        \
    asm volatile("ldmatrix.sync.aligned.m8n8.x4.shared.b16 {%0,%1,%2,%3}, [%4];" \
        : "=r"(r0), "=r"(r1), "=r"(r2), "=r"(r3) : "r"(addr))

// m16n8k8 tf32 MMA, fp32 accumulate (sm_80+ family-portable)
__device__ __forceinline__ void mma_tf32(float* d, const uint32_t* a, const uint32_t* b) {
    asm volatile(
        "mma.sync.aligned.m16n8k8.row.col.f32.tf32.tf32.f32 "
        "{%0,%1,%2,%3}, {%4,%5,%6,%7}, {%8,%9}, {%0,%1,%2,%3};"
        : "+f"(d[0]), "+f"(d[1]), "+f"(d[2]), "+f"(d[3])
        : "r"(a[0]), "r"(a[1]), "r"(a[2]), "r"(a[3]), "r"(b[0]), "r"(b[1]));
}

__device__ __forceinline__ float silu_f(float x) {
    return x / (1.0f + __expf(-x));
}

// ---------------------------------------------------------------------------
// Weight pre-round: out[i] = tf32(in[i])
// ---------------------------------------------------------------------------
__global__ __launch_bounds__(256) void cvt_w_k(
    const float4* __restrict__ in, float4* __restrict__ out, int n4)
{
    int i = blockIdx.x * 256 + threadIdx.x;
    if (i >= n4) return;
    float4 v = in[i];
    out[i] = make_float4(f2tf32f(v.x), f2tf32f(v.y), f2tf32f(v.z), f2tf32f(v.w));
}

// ---------------------------------------------------------------------------
// tf32 tensor-core NT GEMM: C[m,n] = sum_k A[m,k]*B[n,k], epilogue modes:
//  0: C = acc (raw)
//  1: C = acc + Res (raw)
//  2: C = tf32( silu(Res) * acc )        (fused SwiGLU; Res = gate buffer)
//  3: C = tf32( acc * (n0<2048 ? ATT_SCALE : 1) )   (fused QKV post-process)
// ---------------------------------------------------------------------------
#define RS 36
#define TILE_BYTES (128 * RS * 4)
#define STAGE_BYTES (2 * TILE_BYTES)
#define GEMM_SMEM (2 * STAGE_BYTES)

__global__ __launch_bounds__(256, 2) void gemm_tc(
    const float* __restrict__ A, int lda,
    const float* __restrict__ B, int ldb,
    const float* __restrict__ Res,
    float* __restrict__ C, int ldc, int K, int mode)
{
    extern __shared__ __align__(1024) char sm[];
    const uint32_t sbase = smem_u32(sm);
    const int tid  = threadIdx.x;
    const int wid  = tid >> 5, lane = tid & 31;
    const int g    = lane >> 2, t4 = lane & 3;
    const int wm0  = (wid >> 2) * 64;
    const int wn0  = (wid & 3) * 32;
    const int m0   = blockIdx.y * 128;
    const int n0   = blockIdx.x * 128;

    const int j   = lane & 7;
    const int sel = lane >> 3;
    uint32_t offA[4], offB[2];
    #pragma unroll
    for (int mi = 0; mi < 4; mi++)
        offA[mi] = (uint32_t)((wm0 + mi * 16 + (sel & 1) * 8 + j) * 144 + (sel >> 1) * 16);
    #pragma unroll
    for (int np = 0; np < 2; np++)
        offB[np] = (uint32_t)((wn0 + np * 16 + (sel >> 1) * 8 + j) * 144 + (sel & 1) * 16);

    const int r0  = tid >> 3;
    const int seg = tid & 7;
    const float* Ab = A + (size_t)(m0 + r0) * lda + seg * 4;
    const float* Bb = B + (size_t)(n0 + r0) * ldb + seg * 4;
    const uint32_t soff = (uint32_t)(r0 * 144 + seg * 16);

    float acc[4][4][4];
    #pragma unroll
    for (int mi = 0; mi < 4; mi++)
        #pragma unroll
        for (int ni = 0; ni < 4; ni++)
            #pragma unroll
            for (int jj = 0; jj < 4; jj++) acc[mi][ni][jj] = 0.0f;

    const int NC = K / 32;

    {
        const uint32_t sA = sbase + soff;
        const uint32_t sB = sA + TILE_BYTES;
        #pragma unroll
        for (int t = 0; t < 4; t++) {
            cp_async16(sA + t * 32 * 144, Ab + (size_t)(t * 32) * lda);
            cp_async16(sB + t * 32 * 144, Bb + (size_t)(t * 32) * ldb);
        }
        CP_COMMIT();
    }

    for (int c = 0; c < NC; c++) {
        CP_WAIT0();
        __syncthreads();

        if (c + 1 < NC) {
            const uint32_t sA = sbase + ((c + 1) & 1) * STAGE_BYTES + soff;
            const uint32_t sB = sA + TILE_BYTES;
            const float* An = Ab + (size_t)(c + 1) * 32;
            const float* Bn = Bb + (size_t)(c + 1) * 32;
            #pragma unroll
            for (int t = 0; t < 4; t++) {
                cp_async16(sA + t * 32 * 144, An + (size_t)(t * 32) * lda);
                cp_async16(sB + t * 32 * 144, Bn + (size_t)(t * 32) * ldb);
            }
            CP_COMMIT();
        }

        const uint32_t stA = sbase + (c & 1) * STAGE_BYTES;
        const uint32_t stB = stA + TILE_BYTES;

        #pragma unroll
        for (int ks = 0; ks < 4; ks++) {
            uint32_t ua[4][4], ub[4][2];
            #pragma unroll
            for (int mi = 0; mi < 4; mi++)
                LDSM_X4(ua[mi][0], ua[mi][1], ua[mi][2], ua[mi][3],
                        stA + offA[mi] + ks * 32);
            #pragma unroll
            for (int np = 0; np < 2; np++)
                LDSM_X4(ub[2*np][0], ub[2*np][1], ub[2*np+1][0], ub[2*np+1][1],
                        stB + offB[np] + ks * 32);
            #pragma unroll
            for (int mi = 0; mi < 4; mi++)
                #pragma unroll
                for (int ni = 0; ni < 4; ni++)
                    mma_tf32(acc[mi][ni], ua[mi], ub[ni]);
        }
        __syncthreads();
    }

    const float qscale = (mode == 3 && n0 < 2048) ? ATT_SCALE : 1.0f;

    #pragma unroll
    for (int mi = 0; mi < 4; mi++) {
        #pragma unroll
        for (int ni = 0; ni < 4; ni++) {
            const int row = m0 + wm0 + mi * 16 + g;
            const int col = n0 + wn0 + ni * 8 + 2 * t4;
            float2 v0 = make_float2(acc[mi][ni][0], acc[mi][ni][1]);
            float2 v1 = make_float2(acc[mi][ni][2], acc[mi][ni][3]);
            if (mode == 1) {
                float2 e0 = *(const float2*)(Res + (size_t)row * ldc + col);
                float2 e1 = *(const float2*)(Res + (size_t)(row + 8) * ldc + col);
                v0.x += e0.x; v0.y += e0.y;
                v1.x += e1.x; v1.y += e1.y;
            } else if (mode == 2) {
                float2 e0 = *(const float2*)(Res + (size_t)row * ldc + col);
                float2 e1 = *(const float2*)(Res + (size_t)(row + 8) * ldc + col);
                v0.x = f2tf32f(silu_f(e0.x) * v0.x);
                v0.y = f2tf32f(silu_f(e0.y) * v0.y);
                v1.x = f2tf32f(silu_f(e1.x) * v1.x);
                v1.y = f2tf32f(silu_f(e1.y) * v1.y);
            } else if (mode == 3) {
                v0.x = f2tf32f(v0.x * qscale); v0.y = f2tf32f(v0.y * qscale);
                v1.x = f2tf32f(v1.x * qscale); v1.y = f2tf32f(v1.y * qscale);
            }
            *(float2*)(C + (size_t)row * ldc + col)       = v0;
            *(float2*)(C + (size_t)(row + 8) * ldc + col) = v1;
        }
    }
}

// ---------------------------------------------------------------------------
// RMSNorm (tf32-rounded output)
// ---------------------------------------------------------------------------
__global__ __launch_bounds__(256) void rmsnorm_k(
    const float* __restrict__ x, const float* __restrict__ w, float* __restrict__ y)
{
    const int row = blockIdx.x;
    const float4* xr = (const float4*)(x + (size_t)row * H_DIM);
    float4*       yr = (float4*)(y + (size_t)row * H_DIM);
    const float4* w4 = (const float4*)w;
    const int tid = threadIdx.x;

    float4 v0 = xr[tid];
    float4 v1 = xr[tid + 256];
    float s = v0.x*v0.x + v0.y*v0.y + v0.z*v0.z + v0.w*v0.w
            + v1.x*v1.x + v1.y*v1.y + v1.z*v1.z + v1.w*v1.w;

    #pragma unroll
    for (int off = 16; off; off >>= 1) s += __shfl_xor_sync(0xffffffffu, s, off);

    __shared__ float red[8];
    if ((tid & 31) == 0) red[tid >> 5] = s;
    __syncthreads();
    float tot = red[0] + red[1] + red[2] + red[3] + red[4] + red[5] + red[6] + red[7];
    const float inv = rsqrtf(tot * (1.0f / H_DIM) + 1e-6f);

    float4 w0 = w4[tid], w1 = w4[tid + 256];
    float4 o0, o1;
    o0.x = f2tf32f(v0.x * inv * w0.x); o0.y = f2tf32f(v0.y * inv * w0.y);
    o0.z = f2tf32f(v0.z * inv * w0.z); o0.w = f2tf32f(v0.w * inv * w0.w);
    o1.x = f2tf32f(v1.x * inv * w1.x); o1.y = f2tf32f(v1.y * inv * w1.y);
    o1.z = f2tf32f(v1.z * inv * w1.z); o1.w = f2tf32f(v1.w * inv * w1.w);
    yr[tid] = o0;
    yr[tid + 256] = o1;
}

// ---------------------------------------------------------------------------
// Tensor-core causal flash attention (tf32 mma), GQA kvh = h>>1.
// qkv buffer arrives PRE-ROUNDED to tf32 (q also pre-scaled by 1/sqrt(d)),
// so K streams in via cp.async (double-buffered) and V is register-prefetched
// and transposed into smem — per-iteration loads are fully overlapped.
// ---------------------------------------------------------------------------
#define QP 132
#define VP 68
// Qs[128][132] + Ks[2][64][132] + Vts[128][68] + Ps[128][68]
#define FLASH_SMEM ((128*QP + 2*64*QP + 128*VP + 128*VP) * 4)   // 204800

__global__ __launch_bounds__(256, 1) void flash_tc(
    const float* __restrict__ qkv, float* __restrict__ out)
{
    extern __shared__ float smf[];
    float* Qs  = smf;                   // [128][132]
    float* Ks  = Qs + 128 * QP;         // [2][64][132]
    float* Vts = Ks + 2 * 64 * QP;      // [128][68]  d-major (transposed V)
    float* Ps  = Vts + 128 * VP;        // [128][68]

    const int qt = gridDim.x - 1 - blockIdx.x;   // descending qt: causal balance
    const int h  = blockIdx.y;
    const int b  = blockIdx.z;
    const int kvh = h >> 1;
    const int q0 = qt * 128;
    const int tid = threadIdx.x;
    const int wid = tid >> 5, lane = tid & 31;
    const int g = lane >> 2, t4 = lane & 3;
    const int j = lane & 7, sel = lane >> 3;
    const int wm0 = wid * 16;

    const float* qbase = qkv + ((size_t)(b * S_LEN + q0)) * QKV_LD + h * HD;
    const float* kbase = qkv + ((size_t)(b * S_LEN)) * QKV_LD + 2048 + kvh * HD;
    const float* vbase = kbase + 1024;

    // Load Q tile (already scaled + tf32-rounded upstream)
    #pragma unroll
    for (int t = 0; t < 16; t++) {
        int idx = tid + t * 256;
        int r = idx >> 5;
        int c4 = (idx & 31) << 2;
        *(float4*)&Qs[r * QP + c4] = *(const float4*)(qbase + (size_t)r * QKV_LD + c4);
    }

    const uint32_t sQ = smem_u32(Qs), sKb = smem_u32(Ks);
    const uint32_t sV = smem_u32(Vts), sP = smem_u32(Ps);

    // per-thread K cp.async / V load mapping: idx = tid + t*256
    const int kr  = tid >> 2;          // 0..63 (row), 4 segs per row handled by t
    const int ks4 = (tid & 3) << 3;    // seg group: 0,8,16,24 (of 32 16B segs)

    // ldmatrix lane byte-offsets (NT fragment mapping)
    const uint32_t offQA = (uint32_t)((wm0 + (sel & 1) * 8 + j) * (QP * 4) + (sel >> 1) * 16);
    uint32_t offKB[4];
    #pragma unroll
    for (int np = 0; np < 4; np++)
        offKB[np] = (uint32_t)((np * 16 + (sel >> 1) * 8 + j) * (QP * 4) + (sel & 1) * 16);
    const uint32_t offPA = (uint32_t)((wm0 + (sel & 1) * 8 + j) * (VP * 4) + (sel >> 1) * 16);
    uint32_t offVB[8];
    #pragma unroll
    for (int np = 0; np < 8; np++)
        offVB[np] = (uint32_t)((np * 16 + (sel >> 1) * 8 + j) * (VP * 4) + (sel & 1) * 16);

    float m0 = -1e30f, m1 = -1e30f, l0 = 0.0f, l1 = 0.0f;
    float o[16][4];
    #pragma unroll
    for (int nt = 0; nt < 16; nt++)
        #pragma unroll
        for (int c = 0; c < 4; c++) o[nt][c] = 0.0f;

    const int nkt = 2 * qt + 2;
    float4 vreg[8];

    // ---- prologue: K0 via cp.async, V0 via registers ----
    {
        const uint32_t dK = sKb + (uint32_t)(kr * (QP * 4));
        const float* srcK = kbase + (size_t)kr * QKV_LD;
        #pragma unroll
        for (int t = 0; t < 8; t++)
            cp_async16(dK + (ks4 + t) * 16, srcK + (ks4 + t) * 4);
        CP_COMMIT();
        #pragma unroll
        for (int t = 0; t < 8; t++) {
            int idx = tid + t * 256;
            int r = idx >> 5;
            int c4 = (idx & 31) << 2;
            vreg[t] = *(const float4*)(vbase + (size_t)r * QKV_LD + c4);
        }
        CP_WAIT0();
        __syncthreads();
        #pragma unroll
        for (int t = 0; t < 8; t++) {
            int idx = tid + t * 256;
            int r = idx >> 5;
            int c4 = (idx & 31) << 2;
            Vts[(c4 + 0) * VP + r] = vreg[t].x;
            Vts[(c4 + 1) * VP + r] = vreg[t].y;
            Vts[(c4 + 2) * VP + r] = vreg[t].z;
            Vts[(c4 + 3) * VP + r] = vreg[t].w;
        }
        __syncthreads();
    }

    int cur = 0;
    for (int kt = 0; kt < nkt; kt++) {
        // prefetch next K (cp.async) and V (registers)
        if (kt + 1 < nkt) {
            const int k1 = (kt + 1) * 64;
            const uint32_t dK = sKb + (uint32_t)((1 - cur) * 64 * QP * 4 + kr * (QP * 4));
            const float* srcK = kbase + (size_t)(k1 + kr) * QKV_LD;
            #pragma unroll
            for (int t = 0; t < 8; t++)
                cp_async16(dK + (ks4 + t) * 16, srcK + (ks4 + t) * 4);
            CP_COMMIT();
            #pragma unroll
            for (int t = 0; t < 8; t++) {
                int idx = tid + t * 256;
                int r = idx >> 5;
                int c4 = (idx & 31) << 2;
                vreg[t] = *(const float4*)(vbase + (size_t)(k1 + r) * QKV_LD + c4);
            }
        }

        const int k0 = kt * 64;
        const uint32_t sK = sKb + (uint32_t)(cur * 64 * QP * 4);

        // --- S = Q K^T ---
        float s[8][4];
        #pragma unroll
        for (int nt = 0; nt < 8; nt++)
            #pragma unroll
            for (int c = 0; c < 4; c++) s[nt][c] = 0.0f;

        #pragma unroll
        for (int ks = 0; ks < 16; ks++) {
            uint32_t a[4], bb[8][2];
            LDSM_X4(a[0], a[1], a[2], a[3], sQ + offQA + ks * 32);
            #pragma unroll
            for (int np = 0; np < 4; np++)
                LDSM_X4(bb[2*np][0], bb[2*np][1], bb[2*np+1][0], bb[2*np+1][1],
                        sK + offKB[np] + ks * 32);
            #pragma unroll
            for (int nt = 0; nt < 8; nt++)
                mma_tf32(s[nt], a, bb[nt]);
        }

        // --- causal mask (last two k-tiles only) ---
        if (kt >= 2 * qt) {
            const int r0g = q0 + wm0 + g;
            const int r1g = r0g + 8;
            #pragma unroll
            for (int nt = 0; nt < 8; nt++) {
                const int c0 = k0 + nt * 8 + 2 * t4;
                const int c1 = c0 + 1;
                if (c0 > r0g) s[nt][0] = -1e30f;
                if (c1 > r0g) s[nt][1] = -1e30f;
                if (c0 > r1g) s[nt][2] = -1e30f;
                if (c1 > r1g) s[nt][3] = -1e30f;
            }
        }

        // --- online softmax ---
        float mx0 = -1e30f, mx1 = -1e30f;
        #pragma unroll
        for (int nt = 0; nt < 8; nt++) {
            mx0 = fmaxf(mx0, fmaxf(s[nt][0], s[nt][1]));
            mx1 = fmaxf(mx1, fmaxf(s[nt][2], s[nt][3]));
        }
        mx0 = fmaxf(mx0, __shfl_xor_sync(0xffffffffu, mx0, 1));
        mx0 = fmaxf(mx0, __shfl_xor_sync(0xffffffffu, mx0, 2));
        mx1 = fmaxf(mx1, __shfl_xor_sync(0xffffffffu, mx1, 1));
        mx1 = fmaxf(mx1, __shfl_xor_sync(0xffffffffu, mx1, 2));

        const float nm0 = fmaxf(m0, mx0);
        const float nm1 = fmaxf(m1, mx1);
        const float al0 = __expf(m0 - nm0);
        const float al1 = __expf(m1 - nm1);
        m0 = nm0; m1 = nm1;

        float rs0 = 0.0f, rs1 = 0.0f;
        const int prow0 = (wm0 + g) * VP + 2 * t4;
        const int prow1 = (wm0 + g + 8) * VP + 2 * t4;
        #pragma unroll
        for (int nt = 0; nt < 8; nt++) {
            float p0 = __expf(s[nt][0] - nm0);
            float p1 = __expf(s[nt][1] - nm0);
            float p2 = __expf(s[nt][2] - nm1);
            float p3 = __expf(s[nt][3] - nm1);
            rs0 += p0 + p1;
            rs1 += p2 + p3;
            *(float2*)&Ps[prow0 + nt * 8] = make_float2(f2tf32f(p0), f2tf32f(p1));
            *(float2*)&Ps[prow1 + nt * 8] = make_float2(f2tf32f(p2), f2tf32f(p3));
        }
        rs0 += __shfl_xor_sync(0xffffffffu, rs0, 1);
        rs0 += __shfl_xor_sync(0xffffffffu, rs0, 2);
        rs1 += __shfl_xor_sync(0xffffffffu, rs1, 1);
        rs1 += __shfl_xor_sync(0xffffffffu, rs1, 2);
        l0 = l0 * al0 + rs0;
        l1 = l1 * al1 + rs1;

        #pragma unroll
        for (int nt = 0; nt < 16; nt++) {
            o[nt][0] *= al0; o[nt][1] *= al0;
            o[nt][2] *= al1; o[nt][3] *= al1;
        }
        __syncwarp();   // order Ps stores before ldmatrix (warp-private rows)

        // --- O += P V ---
        #pragma unroll
        for (int ks = 0; ks < 8; ks++) {
            uint32_t pa[4], vb[16][2];
            LDSM_X4(pa[0], pa[1], pa[2], pa[3], sP + offPA + ks * 32);
            #pragma unroll
            for (int np = 0; np < 8; np++)
                LDSM_X4(vb[2*np][0], vb[2*np][1], vb[2*np+1][0], vb[2*np+1][1],
                        sV + offVB[np] + ks * 32);
            #pragma unroll
            for (int nt = 0; nt < 16; nt++)
                mma_tf32(o[nt], pa, vb[nt]);
        }

        __syncthreads();   // all warps done reading Vts
        if (kt + 1 < nkt) {
            #pragma unroll
            for (int t = 0; t < 8; t++) {
                int idx = tid + t * 256;
                int r = idx >> 5;
                int c4 = (idx & 31) << 2;
                Vts[(c4 + 0) * VP + r] = vreg[t].x;
                Vts[(c4 + 1) * VP + r] = vreg[t].y;
                Vts[(c4 + 2) * VP + r] = vreg[t].z;
                Vts[(c4 + 3) * VP + r] = vreg[t].w;
            }
            CP_WAIT0();    // next K tile landed (issued a full iteration ago)
        }
        __syncthreads();   // Vts(kt+1) + Ks[nxt] visible
        cur ^= 1;
    }

    // --- normalize and write (tf32-rounded; feeds O-proj GEMM) ---
    const float inv0 = 1.0f / l0;
    const float inv1 = 1.0f / l1;
    const size_t row0 = (size_t)(b * S_LEN + q0 + wm0 + g);
    #pragma unroll
    for (int nt = 0; nt < 16; nt++) {
        const int col = h * HD + nt * 8 + 2 * t4;
        *(float2*)(out + row0 * H_DIM + col) =
            make_float2(f2tf32f(o[nt][0] * inv0), f2tf32f(o[nt][1] * inv0));
        *(float2*)(out + (row0 + 8) * H_DIM + col) =
            make_float2(f2tf32f(o[nt][2] * inv1), f2tf32f(o[nt][3] * inv1));
    }
}

// ---------------------------------------------------------------------------
// Launch
// ---------------------------------------------------------------------------
extern "C" void kernel_launch(void* const* d_in, const int* in_sizes, int n_in,
                              void* d_out, int out_size)
{
    const float* hidden = (const float*)d_in[0];
    const float* q_w    = (const float*)d_in[2];
    const float* k_w    = (const float*)d_in[3];
    const float* v_w    = (const float*)d_in[4];
    const float* o_w    = (const float*)d_in[5];
    const float* gate_w = (const float*)d_in[6];
    const float* up_w   = (const float*)d_in[7];
    const float* down_w = (const float*)d_in[8];
    const float* ln1    = (const float*)d_in[9];
    const float* ln2    = (const float*)d_in[10];
    float* out = (float*)d_out;

    float *xn, *qkv, *attn, *hbuf, *gate, *ff;
    float *wqkv, *wo, *wg, *wu, *wd;
    cudaGetSymbolAddress((void**)&xn,   g_xn);
    cudaGetSymbolAddress((void**)&qkv,  g_qkv);
    cudaGetSymbolAddress((void**)&attn, g_attn);
    cudaGetSymbolAddress((void**)&hbuf, g_h);
    cudaGetSymbolAddress((void**)&gate, g_gate);
    cudaGetSymbolAddress((void**)&ff,   g_ff);
    cudaGetSymbolAddress((void**)&wqkv, g_wqkv);
    cudaGetSymbolAddress((void**)&wo,   g_wo);
    cudaGetSymbolAddress((void**)&wg,   g_wg);
    cudaGetSymbolAddress((void**)&wu,   g_wu);
    cudaGetSymbolAddress((void**)&wd,   g_wd);

    cudaFuncSetAttribute(flash_tc, cudaFuncAttributeMaxDynamicSharedMemorySize, FLASH_SMEM);
    cudaFuncSetAttribute(gemm_tc,  cudaFuncAttributeMaxDynamicSharedMemorySize, GEMM_SMEM);

    // 0) pre-round weights to tf32 (q|k|v concatenated into one buffer)
    {
        auto cvt = [](const float* src, float* dst, size_t n) {
            int n4 = (int)(n / 4);
            cvt_w_k<<<(n4 + 255) / 256, 256>>>((const float4*)src, (float4*)dst, n4);
        };
        cvt(q_w,    wqkv,                        (size_t)2048 * 2048);
        cvt(k_w,    wqkv + (size_t)2048 * 2048,  (size_t)1024 * 2048);
        cvt(v_w,    wqkv + (size_t)3072 * 2048,  (size_t)1024 * 2048);
        cvt(o_w,    wo, (size_t)2048 * 2048);
        cvt(gate_w, wg, (size_t)FF_DIM * 2048);
        cvt(up_w,   wu, (size_t)FF_DIM * 2048);
        cvt(down_w, wd, (size_t)2048 * FF_DIM);
    }

    // 1) rmsnorm(hidden) -> xn (tf32-rounded)
    rmsnorm_k<<<MROWS, 256>>>(hidden, ln1, xn);

    // 2) fused QKV projection -> qkv (scaled q, all tf32-rounded in epilogue)
    gemm_tc<<<dim3(32, 32), 256, GEMM_SMEM>>>(xn, H_DIM, wqkv, H_DIM, nullptr,
                                              qkv, QKV_LD, H_DIM, 3);

    // 3) tensor-core causal flash attention -> attn (tf32-rounded)
    flash_tc<<<dim3(S_LEN / 128, NHEADS, B_SZ), 256, FLASH_SMEM>>>(qkv, attn);

    // 4) O projection + residual -> hbuf
    gemm_tc<<<dim3(16, 32), 256, GEMM_SMEM>>>(attn, H_DIM, wo, H_DIM, hidden,
                                              hbuf, H_DIM, H_DIM, 1);

    // 5) rmsnorm(hbuf) -> xn (tf32-rounded)
    rmsnorm_k<<<MROWS, 256>>>(hbuf, ln2, xn);

    // 6) gate projection (raw) -> gate
    gemm_tc<<<dim3(44, 32), 256, GEMM_SMEM>>>(xn, H_DIM, wg, H_DIM, nullptr,
                                              gate, FF_DIM, H_DIM, 0);

    // 7) up projection with fused SwiGLU epilogue -> ff = tf32(silu(gate)*up)
    gemm_tc<<<dim3(44, 32), 256, GEMM_SMEM>>>(xn, H_DIM, wu, H_DIM, gate,
                                              ff, FF_DIM, H_DIM, 2);

    // 8) down projection + residual -> out
    gemm_tc<<<dim3(16, 32), 256, GEMM_SMEM>>>(ff, FF_DIM, wd, FF_DIM, hbuf,
                                              out, H_DIM, FF_DIM, 1);
}

// round 12
// speedup vs baseline: 5.7270x; 1.4345x over previous
#include <cuda_runtime.h>
#include <cuda_fp16.h>
#include <cstdint>
#include <cstddef>

// Problem constants
#define H_DIM   2048
#define S_LEN   2048
#define B_SZ    2
#define NHEADS  16
#define NKVH    8
#define HD      128
#define FF_DIM  5632
#define MROWS   (B_SZ * S_LEN)          // 4096
#define QKV_LD  4096                    // q(2048) | k(1024) | v(1024)
#define ATT_SCALE 0.08838834764831845f  // 1/sqrt(128)

// ---------------------------------------------------------------------------
// Scratch (activations fp16; residual stream fp32)
// ---------------------------------------------------------------------------
__device__ __half g_xn  [(size_t)MROWS * H_DIM];
__device__ __half g_qkv [(size_t)MROWS * QKV_LD];
__device__ __half g_attn[(size_t)MROWS * H_DIM];
__device__ float  g_h   [(size_t)MROWS * H_DIM];
__device__ float  g_gate[(size_t)MROWS * FF_DIM];
__device__ __half g_ff  [(size_t)MROWS * FF_DIM];
// fp16 weight copies
__device__ __half g_wqkv[(size_t)4096 * 2048];
__device__ __half g_wo[(size_t)2048 * 2048];
__device__ __half g_wg[(size_t)FF_DIM * 2048];
__device__ __half g_wu[(size_t)FF_DIM * 2048];
__device__ __half g_wd[(size_t)2048 * FF_DIM];

// ---------------------------------------------------------------------------
// Helpers (family-portable PTX: cp.async + mma.sync + ldmatrix)
// ---------------------------------------------------------------------------
__device__ __forceinline__ uint32_t smem_u32(const void* p) {
    uint32_t a;
    asm("{ .reg .u64 t; cvta.to.shared.u64 t, %1; cvt.u32.u64 %0, t; }"
        : "=r"(a) : "l"(p));
    return a;
}

__device__ __forceinline__ void cp_async16(uint32_t dst, const void* src) {
    asm volatile("cp.async.cg.shared.global [%0], [%1], 16;"
                 :: "r"(dst), "l"(src) : "memory");
}
#define CP_COMMIT() asm volatile("cp.async.commit_group;" ::: "memory")
#define CP_WAIT0()  asm volatile("cp.async.wait_group 0;" ::: "memory")

#define LDSM_X4(r0, r1, r2, r3, addr)                                        \
    asm volatile("ldmatrix.sync.aligned.m8n8.x4.shared.b16 {%0,%1,%2,%3}, [%4];" \
        : "=r"(r0), "=r"(r1), "=r"(r2), "=r"(r3) : "r"(addr))

// m16n8k16 fp16 MMA, fp32 accumulate (sm_80+ family-portable)
__device__ __forceinline__ void mma_f16(float* d, const uint32_t* a, const uint32_t* b) {
    asm volatile(
        "mma.sync.aligned.m16n8k16.row.col.f32.f16.f16.f32 "
        "{%0,%1,%2,%3}, {%4,%5,%6,%7}, {%8,%9}, {%0,%1,%2,%3};"
        : "+f"(d[0]), "+f"(d[1]), "+f"(d[2]), "+f"(d[3])
        : "r"(a[0]), "r"(a[1]), "r"(a[2]), "r"(a[3]), "r"(b[0]), "r"(b[1]));
}

__device__ __forceinline__ float silu_f(float x) {
    return x / (1.0f + __expf(-x));
}

// ---------------------------------------------------------------------------
// Weight convert: float -> fp16
// ---------------------------------------------------------------------------
__global__ __launch_bounds__(256) void cvt_wh_k(
    const float4* __restrict__ in, __half* __restrict__ out, int n4)
{
    int i = blockIdx.x * 256 + threadIdx.x;
    if (i >= n4) return;
    float4 v = in[i];
    half2* o = (half2*)(out + (size_t)i * 4);
    o[0] = __floats2half2_rn(v.x, v.y);
    o[1] = __floats2half2_rn(v.z, v.w);
}

// ---------------------------------------------------------------------------
// fp16 tensor-core NT GEMM: C[m,n] = sum_k A[m,k]*B[n,k], epilogue modes:
//  0: float C = acc
//  1: float C = acc + Res
//  2: half  C = h( silu(Res) * acc )     (fused SwiGLU; Res = gate, fp32)
//  3: half  C = h( acc * (n0<2048 ? ATT_SCALE : 1) )  (fused QKV post)
// BM=BN=128, BK=64 halves, 8 warps (2x4), warp tile 64x32, cp.async dbuf.
// Smem rows padded to 72 halves (144B = 9x16B, conflict-free ldmatrix).
// ---------------------------------------------------------------------------
#define HTILE_B (128 * 144)              // 18432 bytes per operand tile
#define HSTAGE_B (2 * HTILE_B)
#define GEMM_SMEM (2 * HSTAGE_B)         // 73728

__global__ __launch_bounds__(256, 2) void gemm_h(
    const __half* __restrict__ A, int lda,
    const __half* __restrict__ B, int ldb,
    const float* __restrict__ Res,
    void* __restrict__ Cv, int ldc, int K, int mode)
{
    extern __shared__ __align__(1024) char sm[];
    const uint32_t sbase = smem_u32(sm);
    const int tid  = threadIdx.x;
    const int wid  = tid >> 5, lane = tid & 31;
    const int g    = lane >> 2, t4 = lane & 3;
    const int wm0  = (wid >> 2) * 64;
    const int wn0  = (wid & 3) * 32;
    const int m0   = blockIdx.y * 128;
    const int n0   = blockIdx.x * 128;

    const int j   = lane & 7;
    const int sel = lane >> 3;
    uint32_t offA[4], offB[2];
    #pragma unroll
    for (int mi = 0; mi < 4; mi++)
        offA[mi] = (uint32_t)((wm0 + mi * 16 + (sel & 1) * 8 + j) * 144 + (sel >> 1) * 16);
    #pragma unroll
    for (int np = 0; np < 2; np++)
        offB[np] = (uint32_t)((wn0 + np * 16 + (sel >> 1) * 8 + j) * 144 + (sel & 1) * 16);

    // cp.async map: 128 rows x 8 segs(16B) per operand; 2 threads/row, 4 segs each
    const int r0 = tid >> 1;
    const int sg = (tid & 1) * 4;
    const __half* Ab = A + (size_t)(m0 + r0) * lda + sg * 8;
    const __half* Bb = B + (size_t)(n0 + r0) * ldb + sg * 8;
    const uint32_t soff = (uint32_t)(r0 * 144 + sg * 16);

    float acc[4][4][4];
    #pragma unroll
    for (int mi = 0; mi < 4; mi++)
        #pragma unroll
        for (int ni = 0; ni < 4; ni++)
            #pragma unroll
            for (int jj = 0; jj < 4; jj++) acc[mi][ni][jj] = 0.0f;

    const int NC = K / 64;

    {
        const uint32_t sA = sbase + soff;
        const uint32_t sB = sA + HTILE_B;
        #pragma unroll
        for (int t = 0; t < 4; t++) {
            cp_async16(sA + t * 16, Ab + t * 8);
            cp_async16(sB + t * 16, Bb + t * 8);
        }
        CP_COMMIT();
    }

    for (int c = 0; c < NC; c++) {
        CP_WAIT0();
        __syncthreads();

        if (c + 1 < NC) {
            const uint32_t sA = sbase + ((c + 1) & 1) * HSTAGE_B + soff;
            const uint32_t sB = sA + HTILE_B;
            const __half* An = Ab + (size_t)(c + 1) * 64;
            const __half* Bn = Bb + (size_t)(c + 1) * 64;
            #pragma unroll
            for (int t = 0; t < 4; t++) {
                cp_async16(sA + t * 16, An + t * 8);
                cp_async16(sB + t * 16, Bn + t * 8);
            }
            CP_COMMIT();
        }

        const uint32_t stA = sbase + (c & 1) * HSTAGE_B;
        const uint32_t stB = stA + HTILE_B;

        #pragma unroll
        for (int ks = 0; ks < 4; ks++) {      // 4 k-steps of k16
            uint32_t ua[4][4], ub[4][2];
            #pragma unroll
            for (int mi = 0; mi < 4; mi++)
                LDSM_X4(ua[mi][0], ua[mi][1], ua[mi][2], ua[mi][3],
                        stA + offA[mi] + ks * 32);
            #pragma unroll
            for (int np = 0; np < 2; np++)
                LDSM_X4(ub[2*np][0], ub[2*np][1], ub[2*np+1][0], ub[2*np+1][1],
                        stB + offB[np] + ks * 32);
            #pragma unroll
            for (int mi = 0; mi < 4; mi++)
                #pragma unroll
                for (int ni = 0; ni < 4; ni++)
                    mma_f16(acc[mi][ni], ua[mi], ub[ni]);
        }
        __syncthreads();
    }

    const float qscale = (mode == 3 && n0 < 2048) ? ATT_SCALE : 1.0f;
    float* Cf = (float*)Cv;
    __half* Ch = (__half*)Cv;

    #pragma unroll
    for (int mi = 0; mi < 4; mi++) {
        #pragma unroll
        for (int ni = 0; ni < 4; ni++) {
            const int row = m0 + wm0 + mi * 16 + g;
            const int col = n0 + wn0 + ni * 8 + 2 * t4;
            float2 v0 = make_float2(acc[mi][ni][0], acc[mi][ni][1]);
            float2 v1 = make_float2(acc[mi][ni][2], acc[mi][ni][3]);
            if (mode == 0) {
                *(float2*)(Cf + (size_t)row * ldc + col)       = v0;
                *(float2*)(Cf + (size_t)(row + 8) * ldc + col) = v1;
            } else if (mode == 1) {
                float2 e0 = *(const float2*)(Res + (size_t)row * ldc + col);
                float2 e1 = *(const float2*)(Res + (size_t)(row + 8) * ldc + col);
                v0.x += e0.x; v0.y += e0.y;
                v1.x += e1.x; v1.y += e1.y;
                *(float2*)(Cf + (size_t)row * ldc + col)       = v0;
                *(float2*)(Cf + (size_t)(row + 8) * ldc + col) = v1;
            } else if (mode == 2) {
                float2 e0 = *(const float2*)(Res + (size_t)row * ldc + col);
                float2 e1 = *(const float2*)(Res + (size_t)(row + 8) * ldc + col);
                *(half2*)(Ch + (size_t)row * ldc + col) =
                    __floats2half2_rn(silu_f(e0.x) * v0.x, silu_f(e0.y) * v0.y);
                *(half2*)(Ch + (size_t)(row + 8) * ldc + col) =
                    __floats2half2_rn(silu_f(e1.x) * v1.x, silu_f(e1.y) * v1.y);
            } else {
                *(half2*)(Ch + (size_t)row * ldc + col) =
                    __floats2half2_rn(v0.x * qscale, v0.y * qscale);
                *(half2*)(Ch + (size_t)(row + 8) * ldc + col) =
                    __floats2half2_rn(v1.x * qscale, v1.y * qscale);
            }
        }
    }
}

// ---------------------------------------------------------------------------
// RMSNorm: float in -> fp16 out
// ---------------------------------------------------------------------------
__global__ __launch_bounds__(256) void rmsnorm_k(
    const float* __restrict__ x, const float* __restrict__ w, __half* __restrict__ y)
{
    const int row = blockIdx.x;
    const float4* xr = (const float4*)(x + (size_t)row * H_DIM);
    half2* yr = (half2*)(y + (size_t)row * H_DIM);
    const float4* w4 = (const float4*)w;
    const int tid = threadIdx.x;

    float4 v0 = xr[tid];
    float4 v1 = xr[tid + 256];
    float s = v0.x*v0.x + v0.y*v0.y + v0.z*v0.z + v0.w*v0.w
            + v1.x*v1.x + v1.y*v1.y + v1.z*v1.z + v1.w*v1.w;

    #pragma unroll
    for (int off = 16; off; off >>= 1) s += __shfl_xor_sync(0xffffffffu, s, off);

    __shared__ float red[8];
    if ((tid & 31) == 0) red[tid >> 5] = s;
    __syncthreads();
    float tot = red[0] + red[1] + red[2] + red[3] + red[4] + red[5] + red[6] + red[7];
    const float inv = rsqrtf(tot * (1.0f / H_DIM) + 1e-6f);

    float4 w0 = w4[tid], w1 = w4[tid + 256];
    yr[2*tid]           = __floats2half2_rn(v0.x * inv * w0.x, v0.y * inv * w0.y);
    yr[2*tid + 1]       = __floats2half2_rn(v0.z * inv * w0.z, v0.w * inv * w0.w);
    yr[2*(tid+256)]     = __floats2half2_rn(v1.x * inv * w1.x, v1.y * inv * w1.y);
    yr[2*(tid+256) + 1] = __floats2half2_rn(v1.z * inv * w1.z, v1.w * inv * w1.w);
}

// ---------------------------------------------------------------------------
// fp16 tensor-core causal flash attention, GQA kvh = h>>1.
// qkv arrives fp16 with q pre-scaled. K double-buffered via cp.async;
// V register-prefetched and transposed into smem. fp32 softmax/accum.
// K row = 128 halves = 256B = 16 x 16B segments: 4 threads/row x 4 segs each.
// ---------------------------------------------------------------------------
#define QP 136    // halves per Q/K row (272B = 17*16B)
#define VP 72     // halves per Vt/P row (144B = 9*16B)
// Qs[128][136] + Ks[2][64][136] + Vts[128][72] + Ps[128][72], halves
#define FLASH_SMEM ((128*QP + 2*64*QP + 128*VP + 128*VP) * 2)   // 106496

__global__ __launch_bounds__(256, 1) void flash_h(
    const __half* __restrict__ qkv, __half* __restrict__ out)
{
    extern __shared__ __half smh[];
    __half* Qs  = smh;                   // [128][136]
    __half* Ks  = Qs + 128 * QP;         // [2][64][136]
    __half* Vts = Ks + 2 * 64 * QP;      // [128][72]  d-major (transposed V)
    __half* Ps  = Vts + 128 * VP;        // [128][72]

    const int qt = gridDim.x - 1 - blockIdx.x;
    const int h  = blockIdx.y;
    const int b  = blockIdx.z;
    const int kvh = h >> 1;
    const int q0 = qt * 128;
    const int tid = threadIdx.x;
    const int wid = tid >> 5, lane = tid & 31;
    const int g = lane >> 2, t4 = lane & 3;
    const int j = lane & 7, sel = lane >> 3;
    const int wm0 = wid * 16;

    const __half* qbase = qkv + ((size_t)(b * S_LEN + q0)) * QKV_LD + h * HD;
    const __half* kbase = qkv + ((size_t)(b * S_LEN)) * QKV_LD + 2048 + kvh * HD;
    const __half* vbase = kbase + 1024;

    // Load Q tile (128 rows x 16 segs of 16B)
    #pragma unroll
    for (int t = 0; t < 8; t++) {
        int idx = tid + t * 256;
        int r = idx >> 4;
        int seg = idx & 15;
        *(uint4*)&Qs[r * QP + seg * 8] = *(const uint4*)(qbase + (size_t)r * QKV_LD + seg * 8);
    }

    const uint32_t sQ = smem_u32(Qs), sKb = smem_u32(Ks);
    const uint32_t sV = smem_u32(Vts), sP = smem_u32(Ps);

    // K cp.async map: 64 rows x 16 segs(16B); 4 threads/row, 4 segs each
    const int kr  = tid >> 2;
    const int ksg = (tid & 3) * 4;

    // ldmatrix lane byte-offsets
    const uint32_t offQA = (uint32_t)((wm0 + (sel & 1) * 8 + j) * (QP * 2) + (sel >> 1) * 16);
    uint32_t offKB[4];
    #pragma unroll
    for (int np = 0; np < 4; np++)
        offKB[np] = (uint32_t)((np * 16 + (sel >> 1) * 8 + j) * (QP * 2) + (sel & 1) * 16);
    const uint32_t offPA = (uint32_t)((wm0 + (sel & 1) * 8 + j) * (VP * 2) + (sel >> 1) * 16);
    uint32_t offVB[8];
    #pragma unroll
    for (int np = 0; np < 8; np++)
        offVB[np] = (uint32_t)((np * 16 + (sel >> 1) * 8 + j) * (VP * 2) + (sel & 1) * 16);

    float m0 = -1e30f, m1 = -1e30f, l0 = 0.0f, l1 = 0.0f;
    float o[16][4];
    #pragma unroll
    for (int nt = 0; nt < 16; nt++)
        #pragma unroll
        for (int c = 0; c < 4; c++) o[nt][c] = 0.0f;

    const int nkt = 2 * qt + 2;
    uint4 vreg[4];

    // ---- prologue: K0 via cp.async (full 16 segs/row), V0 via registers ----
    {
        const uint32_t dK = sKb + (uint32_t)(kr * (QP * 2));
        const __half* srcK = kbase + (size_t)kr * QKV_LD;
        #pragma unroll
        for (int t = 0; t < 4; t++)
            cp_async16(dK + (ksg + t) * 16, srcK + (ksg + t) * 8);
        CP_COMMIT();
        #pragma unroll
        for (int t = 0; t < 4; t++) {
            int idx = tid + t * 256;
            int r = idx >> 4;
            int seg = idx & 15;
            vreg[t] = *(const uint4*)(vbase + (size_t)r * QKV_LD + seg * 8);
        }
        CP_WAIT0();
        __syncthreads();
        #pragma unroll
        for (int t = 0; t < 4; t++) {
            int idx = tid + t * 256;
            int r = idx >> 4;
            int dbase = (idx & 15) * 8;
            const __half* hh = (const __half*)&vreg[t];
            #pragma unroll
            for (int i = 0; i < 8; i++) Vts[(dbase + i) * VP + r] = hh[i];
        }
        __syncthreads();
    }

    int cur = 0;
    for (int kt = 0; kt < nkt; kt++) {
        if (kt + 1 < nkt) {
            const int k1 = (kt + 1) * 64;
            const uint32_t dK = sKb + (uint32_t)((1 - cur) * 64 * QP * 2 + kr * (QP * 2));
            const __half* srcK = kbase + (size_t)(k1 + kr) * QKV_LD;
            #pragma unroll
            for (int t = 0; t < 4; t++)
                cp_async16(dK + (ksg + t) * 16, srcK + (ksg + t) * 8);
            CP_COMMIT();
            #pragma unroll
            for (int t = 0; t < 4; t++) {
                int idx = tid + t * 256;
                int r = idx >> 4;
                int seg = idx & 15;
                vreg[t] = *(const uint4*)(vbase + (size_t)(k1 + r) * QKV_LD + seg * 8);
            }
        }

        const int k0 = kt * 64;
        const uint32_t sK = sKb + (uint32_t)(cur * 64 * QP * 2);

        // --- S = Q K^T (16 q-rows x 64 k-cols per warp), HD/16 = 8 k-steps ---
        float s[8][4];
        #pragma unroll
        for (int nt = 0; nt < 8; nt++)
            #pragma unroll
            for (int c = 0; c < 4; c++) s[nt][c] = 0.0f;

        #pragma unroll
        for (int ks = 0; ks < 8; ks++) {
            uint32_t a[4], bb[8][2];
            LDSM_X4(a[0], a[1], a[2], a[3], sQ + offQA + ks * 32);
            #pragma unroll
            for (int np = 0; np < 4; np++)
                LDSM_X4(bb[2*np][0], bb[2*np][1], bb[2*np+1][0], bb[2*np+1][1],
                        sK + offKB[np] + ks * 32);
            #pragma unroll
            for (int nt = 0; nt < 8; nt++)
                mma_f16(s[nt], a, bb[nt]);
        }

        // --- causal mask (last two k-tiles only) ---
        if (kt >= 2 * qt) {
            const int r0g = q0 + wm0 + g;
            const int r1g = r0g + 8;
            #pragma unroll
            for (int nt = 0; nt < 8; nt++) {
                const int c0 = k0 + nt * 8 + 2 * t4;
                const int c1 = c0 + 1;
                if (c0 > r0g) s[nt][0] = -1e30f;
                if (c1 > r0g) s[nt][1] = -1e30f;
                if (c0 > r1g) s[nt][2] = -1e30f;
                if (c1 > r1g) s[nt][3] = -1e30f;
            }
        }

        // --- online softmax ---
        float mx0 = -1e30f, mx1 = -1e30f;
        #pragma unroll
        for (int nt = 0; nt < 8; nt++) {
            mx0 = fmaxf(mx0, fmaxf(s[nt][0], s[nt][1]));
            mx1 = fmaxf(mx1, fmaxf(s[nt][2], s[nt][3]));
        }
        mx0 = fmaxf(mx0, __shfl_xor_sync(0xffffffffu, mx0, 1));
        mx0 = fmaxf(mx0, __shfl_xor_sync(0xffffffffu, mx0, 2));
        mx1 = fmaxf(mx1, __shfl_xor_sync(0xffffffffu, mx1, 1));
        mx1 = fmaxf(mx1, __shfl_xor_sync(0xffffffffu, mx1, 2));

        const float nm0 = fmaxf(m0, mx0);
        const float nm1 = fmaxf(m1, mx1);
        const float al0 = __expf(m0 - nm0);
        const float al1 = __expf(m1 - nm1);
        m0 = nm0; m1 = nm1;

        float rs0 = 0.0f, rs1 = 0.0f;
        const int prow0 = (wm0 + g) * VP + 2 * t4;
        const int prow1 = (wm0 + g + 8) * VP + 2 * t4;
        #pragma unroll
        for (int nt = 0; nt < 8; nt++) {
            float p0 = __expf(s[nt][0] - nm0);
            float p1 = __expf(s[nt][1] - nm0);
            float p2 = __expf(s[nt][2] - nm1);
            float p3 = __expf(s[nt][3] - nm1);
            rs0 += p0 + p1;
            rs1 += p2 + p3;
            *(half2*)&Ps[prow0 + nt * 8] = __floats2half2_rn(p0, p1);
            *(half2*)&Ps[prow1 + nt * 8] = __floats2half2_rn(p2, p3);
        }
        rs0 += __shfl_xor_sync(0xffffffffu, rs0, 1);
        rs0 += __shfl_xor_sync(0xffffffffu, rs0, 2);
        rs1 += __shfl_xor_sync(0xffffffffu, rs1, 1);
        rs1 += __shfl_xor_sync(0xffffffffu, rs1, 2);
        l0 = l0 * al0 + rs0;
        l1 = l1 * al1 + rs1;

        #pragma unroll
        for (int nt = 0; nt < 16; nt++) {
            o[nt][0] *= al0; o[nt][1] *= al0;
            o[nt][2] *= al1; o[nt][3] *= al1;
        }
        __syncwarp();   // Ps rows are warp-private: order stores before ldmatrix

        // --- O += P V (16 q-rows x 128 d-cols per warp), 64/16 = 4 k-steps ---
        #pragma unroll
        for (int ks = 0; ks < 4; ks++) {
            uint32_t pa[4], vb[16][2];
            LDSM_X4(pa[0], pa[1], pa[2], pa[3], sP + offPA + ks * 32);
            #pragma unroll
            for (int np = 0; np < 8; np++)
                LDSM_X4(vb[2*np][0], vb[2*np][1], vb[2*np+1][0], vb[2*np+1][1],
                        sV + offVB[np] + ks * 32);
            #pragma unroll
            for (int nt = 0; nt < 16; nt++)
                mma_f16(o[nt], pa, vb[nt]);
        }

        __syncthreads();   // all warps done reading Vts
        if (kt + 1 < nkt) {
            #pragma unroll
            for (int t = 0; t < 4; t++) {
                int idx = tid + t * 256;
                int r = idx >> 4;
                int dbase = (idx & 15) * 8;
                const __half* hh = (const __half*)&vreg[t];
                #pragma unroll
                for (int i = 0; i < 8; i++) Vts[(dbase + i) * VP + r] = hh[i];
            }
            CP_WAIT0();    // next K landed (issued a full iteration ago)
        }
        __syncthreads();
        cur ^= 1;
    }

    // --- normalize and write fp16 (feeds O-proj GEMM) ---
    const float inv0 = 1.0f / l0;
    const float inv1 = 1.0f / l1;
    const size_t row0 = (size_t)(b * S_LEN + q0 + wm0 + g);
    #pragma unroll
    for (int nt = 0; nt < 16; nt++) {
        const int col = h * HD + nt * 8 + 2 * t4;
        *(half2*)(out + row0 * H_DIM + col) =
            __floats2half2_rn(o[nt][0] * inv0, o[nt][1] * inv0);
        *(half2*)(out + (row0 + 8) * H_DIM + col) =
            __floats2half2_rn(o[nt][2] * inv1, o[nt][3] * inv1);
    }
}

// ---------------------------------------------------------------------------
// Launch
// ---------------------------------------------------------------------------
extern "C" void kernel_launch(void* const* d_in, const int* in_sizes, int n_in,
                              void* d_out, int out_size)
{
    const float* hidden = (const float*)d_in[0];
    const float* q_w    = (const float*)d_in[2];
    const float* k_w    = (const float*)d_in[3];
    const float* v_w    = (const float*)d_in[4];
    const float* o_w    = (const float*)d_in[5];
    const float* gate_w = (const float*)d_in[6];
    const float* up_w   = (const float*)d_in[7];
    const float* down_w = (const float*)d_in[8];
    const float* ln1    = (const float*)d_in[9];
    const float* ln2    = (const float*)d_in[10];
    float* out = (float*)d_out;

    __half *xn, *qkv, *attn, *ff, *wqkv, *wo, *wg, *wu, *wd;
    float *hbuf, *gate;
    cudaGetSymbolAddress((void**)&xn,   g_xn);
    cudaGetSymbolAddress((void**)&qkv,  g_qkv);
    cudaGetSymbolAddress((void**)&attn, g_attn);
    cudaGetSymbolAddress((void**)&hbuf, g_h);
    cudaGetSymbolAddress((void**)&gate, g_gate);
    cudaGetSymbolAddress((void**)&ff,   g_ff);
    cudaGetSymbolAddress((void**)&wqkv, g_wqkv);
    cudaGetSymbolAddress((void**)&wo,   g_wo);
    cudaGetSymbolAddress((void**)&wg,   g_wg);
    cudaGetSymbolAddress((void**)&wu,   g_wu);
    cudaGetSymbolAddress((void**)&wd,   g_wd);

    cudaFuncSetAttribute(flash_h, cudaFuncAttributeMaxDynamicSharedMemorySize, FLASH_SMEM);
    cudaFuncSetAttribute(gemm_h,  cudaFuncAttributeMaxDynamicSharedMemorySize, GEMM_SMEM);

    // 0) convert weights to fp16 (q|k|v concatenated)
    {
        auto cvt = [](const float* src, __half* dst, size_t n) {
            int n4 = (int)(n / 4);
            cvt_wh_k<<<(n4 + 255) / 256, 256>>>((const float4*)src, dst, n4);
        };
        cvt(q_w,    wqkv,                       (size_t)2048 * 2048);
        cvt(k_w,    wqkv + (size_t)2048 * 2048, (size_t)1024 * 2048);
        cvt(v_w,    wqkv + (size_t)3072 * 2048, (size_t)1024 * 2048);
        cvt(o_w,    wo, (size_t)2048 * 2048);
        cvt(gate_w, wg, (size_t)FF_DIM * 2048);
        cvt(up_w,   wu, (size_t)FF_DIM * 2048);
        cvt(down_w, wd, (size_t)2048 * FF_DIM);
    }

    // 1) rmsnorm(hidden) -> xn (fp16)
    rmsnorm_k<<<MROWS, 256>>>(hidden, ln1, xn);

    // 2) fused QKV projection -> qkv (fp16, q pre-scaled)
    gemm_h<<<dim3(32, 32), 256, GEMM_SMEM>>>(xn, H_DIM, wqkv, H_DIM, nullptr,
                                             qkv, QKV_LD, H_DIM, 3);

    // 3) fp16 tensor-core causal flash attention -> attn
    flash_h<<<dim3(S_LEN / 128, NHEADS, B_SZ), 256, FLASH_SMEM>>>(qkv, attn);

    // 4) O projection + residual -> hbuf (fp32)
    gemm_h<<<dim3(16, 32), 256, GEMM_SMEM>>>(attn, H_DIM, wo, H_DIM, hidden,
                                             hbuf, H_DIM, H_DIM, 1);

    // 5) rmsnorm(hbuf) -> xn (fp16)
    rmsnorm_k<<<MROWS, 256>>>(hbuf, ln2, xn);

    // 6) gate projection -> gate (fp32 raw)
    gemm_h<<<dim3(44, 32), 256, GEMM_SMEM>>>(xn, H_DIM, wg, H_DIM, nullptr,
                                             gate, FF_DIM, H_DIM, 0);

    // 7) up projection + fused SwiGLU -> ff = h(silu(gate)*up) (fp16)
    gemm_h<<<dim3(44, 32), 256, GEMM_SMEM>>>(xn, H_DIM, wu, H_DIM, gate,
                                             ff, FF_DIM, H_DIM, 2);

    // 8) down projection + residual -> out (fp32)
    gemm_h<<<dim3(16, 32), 256, GEMM_SMEM>>>(ff, FF_DIM, wd, FF_DIM, hbuf,
                                             out, H_DIM, FF_DIM, 1);
}